// round 6
// baseline (speedup 1.0000x reference)
#include <cuda_runtime.h>
#include <cstdint>
#include <math.h>

#define T_STEPS 1024
#define A_DIM   64
#define H_DIM   2048
#define G3      (3 * H_DIM)

// ---------------- persistent device scratch (no allocations allowed) ----------------
__device__ float    g_GI[T_STEPS * G3];     // precomputed input gates (incl. b_ih), 25.2 MB
__device__ float    g_S [T_STEPS * H_DIM];  // s2 per step for deferred mean/std GEMMs, 8.4 MB
__device__ float    g_h [H_DIM];            // carried state (= previous s2)
__device__ float    g_s0[H_DIM];
__device__ float    g_s1[H_DIM];
__device__ unsigned g_barcnt;               // monotonic grid barrier counter

// ---------------- helpers ----------------
__device__ __forceinline__ float sigmoidf_(float x) { return 1.0f / (1.0f + expf(-x)); }
__device__ __forceinline__ float eluf_(float x)     { return x > 0.0f ? x : expm1f(x); }

// Grid-wide barrier: monotonic counter, all NB blocks co-resident (1 CTA/SM).
__device__ __forceinline__ void grid_bar(unsigned nb, unsigned& it)
{
    __threadfence();          // release: make prior global stores device-visible
    __syncthreads();          // whole block fenced before arrival
    it += 1;
    if (threadIdx.x == 0) {
        atomicAdd(&g_barcnt, 1u);
        const unsigned tgt = it * nb;
        volatile unsigned* p = &g_barcnt;   // volatile: spin load must re-execute
        while (*p < tgt) { }
        __threadfence();      // acquire
    }
    __syncthreads();
}

// ---------------- init kernel (runs each graph replay: resets barrier + state) ------
__global__ void reset_kernel(const float* __restrict__ state)
{
    int i = blockIdx.x * blockDim.x + threadIdx.x;
    if (i < H_DIM) g_h[i] = state[i];
    if (i == 0)    g_barcnt = 0u;
}

// ---------------- generic C[m][n] = act( sum_k A[m][k]*B[n][k] + bias[n] ) ----------
// Tiles: BM=BN=64, BK=16, 256 threads, 4x4 micro-tile. All dims divide evenly here.
__global__ void __launch_bounds__(256) gemm_bias_act(
    const float* __restrict__ A, const float* __restrict__ B,
    const float* __restrict__ bias, float* __restrict__ C,
    int M, int N, int K, int act)
{
    __shared__ __align__(16) float As[16][68];
    __shared__ __align__(16) float Bs[16][68];

    const int tid = threadIdx.x;
    const int tx  = tid & 15;          // n micro index
    const int ty  = tid >> 4;          // m micro index
    const int n0  = blockIdx.x * 64;
    const int m0  = blockIdx.y * 64;

    float c[4][4] = {};

    for (int k0 = 0; k0 < K; k0 += 16) {
        #pragma unroll
        for (int idx = tid; idx < 64 * 16; idx += 256) {
            int m  = idx >> 4;
            int kk = idx & 15;
            As[kk][m] = A[(size_t)(m0 + m) * K + k0 + kk];
            Bs[kk][m] = B[(size_t)(n0 + m) * K + k0 + kk];
        }
        __syncthreads();

        #pragma unroll
        for (int kk = 0; kk < 16; ++kk) {
            float4 a4 = *reinterpret_cast<const float4*>(&As[kk][ty * 4]);
            float4 b4 = *reinterpret_cast<const float4*>(&Bs[kk][tx * 4]);
            c[0][0] += a4.x * b4.x; c[0][1] += a4.x * b4.y; c[0][2] += a4.x * b4.z; c[0][3] += a4.x * b4.w;
            c[1][0] += a4.y * b4.x; c[1][1] += a4.y * b4.y; c[1][2] += a4.y * b4.z; c[1][3] += a4.y * b4.w;
            c[2][0] += a4.z * b4.x; c[2][1] += a4.z * b4.y; c[2][2] += a4.z * b4.z; c[2][3] += a4.z * b4.w;
            c[3][0] += a4.w * b4.x; c[3][1] += a4.w * b4.y; c[3][2] += a4.w * b4.z; c[3][3] += a4.w * b4.w;
        }
        __syncthreads();
    }

    #pragma unroll
    for (int i = 0; i < 4; ++i) {
        #pragma unroll
        for (int j = 0; j < 4; ++j) {
            int m = m0 + ty * 4 + i;
            int n = n0 + tx * 4 + j;
            float v = c[i][j] + bias[n];
            if (act == 1) v = (v > 20.0f) ? v : log1pf(expf(v));   // softplus
            C[(size_t)m * N + n] = v;
        }
    }
}

// ---------------- persistent recurrent kernel ----------------
// grid = NB (= #SMs), 1024 threads, 1 CTA per SM (co-resident by construction).
// Per step: P1 GRU (warp per hidden unit: 3 dot products), P2 fc1, P3 fc2.
__global__ void __launch_bounds__(1024, 1) recurrent_kernel(
    const float* __restrict__ Whh,  const float* __restrict__ bhh,
    const float* __restrict__ fc1w, const float* __restrict__ fc1b,
    const float* __restrict__ fc2w, const float* __restrict__ fc2b,
    int NB)
{
    __shared__ __align__(16) float smv[H_DIM];   // staged vector (h / s0 / s1)

    const int tid  = threadIdx.x;
    const int bid  = blockIdx.x;
    const int wid  = tid >> 5;
    const int lane = tid & 31;
    const unsigned nb = (unsigned)NB;
    unsigned barit = 0;

    // row handled by this warp in every phase (block-major so SMs stay balanced)
    const int row = wid * NB + bid;

    for (int t = 0; t < T_STEPS; ++t) {
        // ---------- stage h into smem ----------
        for (int i = tid * 4; i < H_DIM; i += 4096) {
            float4 v = __ldcg(reinterpret_cast<const float4*>(g_h + i));
            *reinterpret_cast<float4*>(smv + i) = v;
        }
        __syncthreads();

        // ---------- P1: GRU cell ----------
        if (row < H_DIM) {
            const float* w0 = Whh + (size_t)row * H_DIM;
            const float* w1 = Whh + (size_t)(row +     H_DIM) * H_DIM;
            const float* w2 = Whh + (size_t)(row + 2 * H_DIM) * H_DIM;
            float a0 = 0.f, a1 = 0.f, a2 = 0.f;
            #pragma unroll 4
            for (int k = lane * 4; k < H_DIM; k += 128) {
                float4 hv = *reinterpret_cast<const float4*>(smv + k);
                float4 x0 = *reinterpret_cast<const float4*>(w0 + k);
                float4 x1 = *reinterpret_cast<const float4*>(w1 + k);
                float4 x2 = *reinterpret_cast<const float4*>(w2 + k);
                a0 += x0.x * hv.x + x0.y * hv.y + x0.z * hv.z + x0.w * hv.w;
                a1 += x1.x * hv.x + x1.y * hv.y + x1.z * hv.z + x1.w * hv.w;
                a2 += x2.x * hv.x + x2.y * hv.y + x2.z * hv.z + x2.w * hv.w;
            }
            #pragma unroll
            for (int o = 16; o > 0; o >>= 1) {
                a0 += __shfl_xor_sync(0xffffffffu, a0, o);
                a1 += __shfl_xor_sync(0xffffffffu, a1, o);
                a2 += __shfl_xor_sync(0xffffffffu, a2, o);
            }
            if (lane == 0) {
                const float* gi = g_GI + (size_t)t * G3;
                float ir = gi[row], iz = gi[row + H_DIM], in_ = gi[row + 2 * H_DIM];
                float hr = a0 + bhh[row];
                float hz = a1 + bhh[row + H_DIM];
                float hn = a2 + bhh[row + 2 * H_DIM];
                float r  = sigmoidf_(ir + hr);
                float z  = sigmoidf_(iz + hz);
                float n  = tanhf(in_ + r * hn);
                float hp = smv[row];
                float hnew = (1.0f - z) * n + z * hp;
                __stcg(&g_s0[row], eluf_(hnew));
            }
        }
        grid_bar(nb, barit);

        // ---------- stage s0 ----------
        for (int i = tid * 4; i < H_DIM; i += 4096) {
            float4 v = __ldcg(reinterpret_cast<const float4*>(g_s0 + i));
            *reinterpret_cast<float4*>(smv + i) = v;
        }
        __syncthreads();

        // ---------- P2: fc1 ----------
        if (row < H_DIM) {
            const float* w = fc1w + (size_t)row * H_DIM;
            float a = 0.f;
            #pragma unroll 4
            for (int k = lane * 4; k < H_DIM; k += 128) {
                float4 sv = *reinterpret_cast<const float4*>(smv + k);
                float4 x  = *reinterpret_cast<const float4*>(w + k);
                a += x.x * sv.x + x.y * sv.y + x.z * sv.z + x.w * sv.w;
            }
            #pragma unroll
            for (int o = 16; o > 0; o >>= 1) a += __shfl_xor_sync(0xffffffffu, a, o);
            if (lane == 0) __stcg(&g_s1[row], eluf_(a + fc1b[row]));
        }
        grid_bar(nb, barit);

        // ---------- stage s1 ----------
        for (int i = tid * 4; i < H_DIM; i += 4096) {
            float4 v = __ldcg(reinterpret_cast<const float4*>(g_s1 + i));
            *reinterpret_cast<float4*>(smv + i) = v;
        }
        __syncthreads();

        // ---------- P3: fc2 (result is next h and stored as S[t]) ----------
        if (row < H_DIM) {
            const float* w = fc2w + (size_t)row * H_DIM;
            float a = 0.f;
            #pragma unroll 4
            for (int k = lane * 4; k < H_DIM; k += 128) {
                float4 sv = *reinterpret_cast<const float4*>(smv + k);
                float4 x  = *reinterpret_cast<const float4*>(w + k);
                a += x.x * sv.x + x.y * sv.y + x.z * sv.z + x.w * sv.w;
            }
            #pragma unroll
            for (int o = 16; o > 0; o >>= 1) a += __shfl_xor_sync(0xffffffffu, a, o);
            if (lane == 0) {
                float s2 = eluf_(a + fc2b[row]);
                __stcg(&g_h[row], s2);
                g_S[(size_t)t * H_DIM + row] = s2;   // read by epilogue kernel (after boundary)
            }
        }
        grid_bar(nb, barit);
    }
}

// ---------------- launch ----------------
extern "C" void kernel_launch(void* const* d_in, const int* in_sizes, int n_in,
                              void* d_out, int out_size)
{
    (void)n_in; (void)out_size;

    // ---- input mapping: support both plausible metadata orderings, keyed on sizes ----
    const float *actions, *state, *Wih, *Whh, *bih, *bhh;
    const float *fc1w, *fc1b, *fc2w, *fc2b, *meanw, *meanb, *stdw, *stdb;

    if (in_sizes[0] == T_STEPS * A_DIM) {
        // declaration / dict order:
        // actions, state, W_ih, W_hh, b_ih, b_hh, fc1_w, fc1_b, fc2_w, fc2_b,
        // mean_w, mean_b, std_w, std_b
        actions = (const float*)d_in[0];  state = (const float*)d_in[1];
        Wih     = (const float*)d_in[2];  Whh   = (const float*)d_in[3];
        bih     = (const float*)d_in[4];  bhh   = (const float*)d_in[5];
        fc1w    = (const float*)d_in[6];  fc1b  = (const float*)d_in[7];
        fc2w    = (const float*)d_in[8];  fc2b  = (const float*)d_in[9];
        meanw   = (const float*)d_in[10]; meanb = (const float*)d_in[11];
        stdw    = (const float*)d_in[12]; stdb  = (const float*)d_in[13];
    } else {
        // alphabetical (ASCII: 'W' < 'a' < 'b' < 'f' < 'm' < 's'):
        // W_hh, W_ih, actions, b_hh, b_ih, fc1_b, fc1_w, fc2_b, fc2_w,
        // mean_b, mean_w, state, std_b, std_w
        Whh     = (const float*)d_in[0];  Wih   = (const float*)d_in[1];
        actions = (const float*)d_in[2];  bhh   = (const float*)d_in[3];
        bih     = (const float*)d_in[4];  fc1b  = (const float*)d_in[5];
        fc1w    = (const float*)d_in[6];  fc2b  = (const float*)d_in[7];
        fc2w    = (const float*)d_in[8];  meanb = (const float*)d_in[9];
        meanw   = (const float*)d_in[10]; state = (const float*)d_in[11];
        stdb    = (const float*)d_in[12]; stdw  = (const float*)d_in[13];
    }
    float* out = (float*)d_out;

    int dev = 0;
    cudaGetDevice(&dev);
    int nsm = 148;
    cudaDeviceGetAttribute(&nsm, cudaDevAttrMultiProcessorCount, dev);
    if (nsm < 64) nsm = 64;           // mapping requires NB >= 64 (2048/32 warps)

    float* gi = nullptr;  cudaGetSymbolAddress((void**)&gi, g_GI);
    float* S  = nullptr;  cudaGetSymbolAddress((void**)&S,  g_S);

    // 1) reset barrier + initial state (every replay)
    reset_kernel<<<2, 1024>>>(state);

    // 2) precompute input gates: GI[t][g] = actions[t] . W_ih[g] + b_ih[g]
    {
        dim3 grid(G3 / 64, T_STEPS / 64);
        gemm_bias_act<<<grid, 256>>>(actions, Wih, bih, gi, T_STEPS, G3, A_DIM, 0);
    }

    // 3) sequential recurrence (persistent, grid-barrier synced)
    recurrent_kernel<<<nsm, 1024>>>(Whh, bhh, fc1w, fc1b, fc2w, fc2b, nsm);

    // 4) deferred heads: means (identity) and stds (softplus)
    {
        dim3 grid(H_DIM / 64, T_STEPS / 64);
        gemm_bias_act<<<grid, 256>>>(S, meanw, meanb, out, T_STEPS, H_DIM, H_DIM, 0);
        gemm_bias_act<<<grid, 256>>>(S, stdw,  stdb,  out + (size_t)T_STEPS * H_DIM,
                                     T_STEPS, H_DIM, H_DIM, 1);
    }
}

// round 9
// speedup vs baseline: 1.2733x; 1.2733x over previous
#include <cuda_runtime.h>
#include <cuda_fp16.h>
#include <cstdint>
#include <math.h>

#define T_STEPS 1024
#define A_DIM   64
#define H_DIM   2048
#define G3      (3 * H_DIM)

// ---------------- persistent device scratch (no allocations allowed) ----------------
__device__ float    g_GI[T_STEPS * G3];       // precomputed input gates (incl. b_ih)
__device__ float    g_S [T_STEPS * H_DIM];    // s2 per step for deferred mean/std GEMMs
__device__ float    g_h [H_DIM];              // carried state (= previous s2)
__device__ float    g_s0[H_DIM];
__device__ float    g_s1[H_DIM];
__device__ unsigned g_barcnt;                 // monotonic grid barrier counter
// fp16 copies of recurrent weights (converted every replay; deterministic)
__device__ __half   g_whh_h[G3 * H_DIM];      // 25.2 MB
__device__ __half   g_fc1_h[H_DIM * H_DIM];   // 8.4 MB
__device__ __half   g_fc2_h[H_DIM * H_DIM];   // 8.4 MB

// ---------------- helpers ----------------
__device__ __forceinline__ float sigmoidf_(float x) { return 1.0f / (1.0f + expf(-x)); }
__device__ __forceinline__ float eluf_(float x)     { return x > 0.0f ? x : expm1f(x); }

// dot of 8 fp16 weights (packed uint4) with 8 fp32 smem values
__device__ __forceinline__ float dot8h(uint4 u, const float* sv)
{
    const __half2* h2 = reinterpret_cast<const __half2*>(&u);
    float2 f0 = __half22float2(h2[0]);
    float2 f1 = __half22float2(h2[1]);
    float2 f2 = __half22float2(h2[2]);
    float2 f3 = __half22float2(h2[3]);
    float4 s0 = *reinterpret_cast<const float4*>(sv);
    float4 s1 = *reinterpret_cast<const float4*>(sv + 4);
    return f0.x*s0.x + f0.y*s0.y + f1.x*s0.z + f1.y*s0.w
         + f2.x*s1.x + f2.y*s1.y + f3.x*s1.z + f3.y*s1.w;
}

// Grid-wide barrier: monotonic counter, all NB blocks co-resident (1 CTA/SM).
__device__ __forceinline__ void grid_bar(unsigned nb, unsigned& it)
{
    __threadfence();
    __syncthreads();
    it += 1;
    if (threadIdx.x == 0) {
        atomicAdd(&g_barcnt, 1u);
        const unsigned tgt = it * nb;
        volatile unsigned* p = &g_barcnt;
        while (*p < tgt) { }
        __threadfence();
    }
    __syncthreads();
}

// ---------------- init kernel (each replay: resets barrier + state) ------
__global__ void reset_kernel(const float* __restrict__ state)
{
    int i = blockIdx.x * blockDim.x + threadIdx.x;
    if (i < H_DIM) g_h[i] = state[i];
    if (i == 0)    g_barcnt = 0u;
}

// ---------------- fp32 -> fp16 weight conversion (grid-stride) ----------------
__global__ void __launch_bounds__(256) convert_h_kernel(
    const float* __restrict__ src, __half* __restrict__ dst, int n)
{
    for (int i = (blockIdx.x * blockDim.x + threadIdx.x) * 4; i < n;
         i += gridDim.x * blockDim.x * 4) {
        float4 v = *reinterpret_cast<const float4*>(src + i);
        __half2 a = __floats2half2_rn(v.x, v.y);
        __half2 b = __floats2half2_rn(v.z, v.w);
        uint32_t* d = reinterpret_cast<uint32_t*>(dst + i);
        d[0] = *reinterpret_cast<uint32_t*>(&a);
        d[1] = *reinterpret_cast<uint32_t*>(&b);
    }
}

// ---------------- generic C[m][n] = act( sum_k A[m][k]*B[n][k] + bias[n] ) ----------
__global__ void __launch_bounds__(256) gemm_bias_act(
    const float* __restrict__ A, const float* __restrict__ B,
    const float* __restrict__ bias, float* __restrict__ C,
    int M, int N, int K, int act)
{
    __shared__ __align__(16) float As[16][68];
    __shared__ __align__(16) float Bs[16][68];

    const int tid = threadIdx.x;
    const int tx  = tid & 15;
    const int ty  = tid >> 4;
    const int n0  = blockIdx.x * 64;
    const int m0  = blockIdx.y * 64;

    float c[4][4] = {};

    for (int k0 = 0; k0 < K; k0 += 16) {
        #pragma unroll
        for (int idx = tid; idx < 64 * 16; idx += 256) {
            int m  = idx >> 4;
            int kk = idx & 15;
            As[kk][m] = A[(size_t)(m0 + m) * K + k0 + kk];
            Bs[kk][m] = B[(size_t)(n0 + m) * K + k0 + kk];
        }
        __syncthreads();

        #pragma unroll
        for (int kk = 0; kk < 16; ++kk) {
            float4 a4 = *reinterpret_cast<const float4*>(&As[kk][ty * 4]);
            float4 b4 = *reinterpret_cast<const float4*>(&Bs[kk][tx * 4]);
            c[0][0] += a4.x * b4.x; c[0][1] += a4.x * b4.y; c[0][2] += a4.x * b4.z; c[0][3] += a4.x * b4.w;
            c[1][0] += a4.y * b4.x; c[1][1] += a4.y * b4.y; c[1][2] += a4.y * b4.z; c[1][3] += a4.y * b4.w;
            c[2][0] += a4.z * b4.x; c[2][1] += a4.z * b4.y; c[2][2] += a4.z * b4.z; c[2][3] += a4.z * b4.w;
            c[3][0] += a4.w * b4.x; c[3][1] += a4.w * b4.y; c[3][2] += a4.w * b4.z; c[3][3] += a4.w * b4.w;
        }
        __syncthreads();
    }

    #pragma unroll
    for (int i = 0; i < 4; ++i) {
        #pragma unroll
        for (int j = 0; j < 4; ++j) {
            int m = m0 + ty * 4 + i;
            int n = n0 + tx * 4 + j;
            float v = c[i][j] + bias[n];
            if (act == 1) v = (v > 20.0f) ? v : log1pf(expf(v));   // softplus
            C[(size_t)m * N + n] = v;
        }
    }
}

// ---------------- persistent recurrent kernel (fp16 weights) ----------------
// grid = NB (= #SMs), 512 threads (16 warps), 1 CTA/SM, 128 regs/thread budget.
__global__ void __launch_bounds__(512, 1) recurrent_kernel(
    const float* __restrict__ bhh,  const float* __restrict__ fc1b,
    const float* __restrict__ fc2b, int NB)
{
    __shared__ __align__(16) float smv[H_DIM];

    const int tid  = threadIdx.x;
    const int bid  = blockIdx.x;
    const int wid  = tid >> 5;
    const int lane = tid & 31;
    const unsigned nb = (unsigned)NB;
    unsigned barit = 0;

    // row handled by this warp in every phase (block-major: SMs stay balanced)
    const int row   = wid * NB + bid;
    const bool live = (row < H_DIM);
    const int kb    = lane * 8;                 // per-lane K base (8 halfs per uint4)

    const __half* w0 = g_whh_h + (size_t)row * H_DIM;
    const __half* w1 = g_whh_h + (size_t)(row +     H_DIM) * H_DIM;
    const __half* w2 = g_whh_h + (size_t)(row + 2 * H_DIM) * H_DIM;
    const __half* wf1 = g_fc1_h + (size_t)row * H_DIM;
    const __half* wf2 = g_fc2_h + (size_t)row * H_DIM;

    for (int t = 0; t < T_STEPS; ++t) {
        // ---------- stage h into smem (512 threads x float4 = 2048) ----------
        {
            float4 v = __ldcg(reinterpret_cast<const float4*>(g_h + tid * 4));
            *reinterpret_cast<float4*>(smv + tid * 4) = v;
        }
        __syncthreads();

        // ---------- P1: GRU cell (3 gate rows per warp; 24 loads in flight) ----------
        if (live) {
            float a0 = 0.f, a1 = 0.f, a2 = 0.f;
            #pragma unroll
            for (int it = 0; it < 8; ++it) {
                const int k = kb + it * 256;
                uint4 u0 = *reinterpret_cast<const uint4*>(w0 + k);
                uint4 u1 = *reinterpret_cast<const uint4*>(w1 + k);
                uint4 u2 = *reinterpret_cast<const uint4*>(w2 + k);
                a0 += dot8h(u0, smv + k);
                a1 += dot8h(u1, smv + k);
                a2 += dot8h(u2, smv + k);
            }
            #pragma unroll
            for (int o = 16; o > 0; o >>= 1) {
                a0 += __shfl_xor_sync(0xffffffffu, a0, o);
                a1 += __shfl_xor_sync(0xffffffffu, a1, o);
                a2 += __shfl_xor_sync(0xffffffffu, a2, o);
            }
            if (lane == 0) {
                const float* gi = g_GI + (size_t)t * G3;
                float ir = gi[row], iz = gi[row + H_DIM], in_ = gi[row + 2 * H_DIM];
                float hr = a0 + bhh[row];
                float hz = a1 + bhh[row + H_DIM];
                float hn = a2 + bhh[row + 2 * H_DIM];
                float r  = sigmoidf_(ir + hr);
                float z  = sigmoidf_(iz + hz);
                float n  = tanhf(in_ + r * hn);
                float hp = smv[row];
                float hnew = (1.0f - z) * n + z * hp;
                __stcg(&g_s0[row], eluf_(hnew));
            }
        }
        grid_bar(nb, barit);

        // ---------- stage s0 ----------
        {
            float4 v = __ldcg(reinterpret_cast<const float4*>(g_s0 + tid * 4));
            *reinterpret_cast<float4*>(smv + tid * 4) = v;
        }
        __syncthreads();

        // ---------- P2: fc1 ----------
        if (live) {
            float a = 0.f, b = 0.f;
            #pragma unroll
            for (int it = 0; it < 8; it += 2) {
                const int k0 = kb + it * 256;
                const int k1 = kb + (it + 1) * 256;
                uint4 u0 = *reinterpret_cast<const uint4*>(wf1 + k0);
                uint4 u1 = *reinterpret_cast<const uint4*>(wf1 + k1);
                a += dot8h(u0, smv + k0);
                b += dot8h(u1, smv + k1);
            }
            a += b;
            #pragma unroll
            for (int o = 16; o > 0; o >>= 1) a += __shfl_xor_sync(0xffffffffu, a, o);
            if (lane == 0) __stcg(&g_s1[row], eluf_(a + fc1b[row]));
        }
        grid_bar(nb, barit);

        // ---------- stage s1 ----------
        {
            float4 v = __ldcg(reinterpret_cast<const float4*>(g_s1 + tid * 4));
            *reinterpret_cast<float4*>(smv + tid * 4) = v;
        }
        __syncthreads();

        // ---------- P3: fc2 (result is next h, and S[t]) ----------
        if (live) {
            float a = 0.f, b = 0.f;
            #pragma unroll
            for (int it = 0; it < 8; it += 2) {
                const int k0 = kb + it * 256;
                const int k1 = kb + (it + 1) * 256;
                uint4 u0 = *reinterpret_cast<const uint4*>(wf2 + k0);
                uint4 u1 = *reinterpret_cast<const uint4*>(wf2 + k1);
                a += dot8h(u0, smv + k0);
                b += dot8h(u1, smv + k1);
            }
            a += b;
            #pragma unroll
            for (int o = 16; o > 0; o >>= 1) a += __shfl_xor_sync(0xffffffffu, a, o);
            if (lane == 0) {
                float s2 = eluf_(a + fc2b[row]);
                __stcg(&g_h[row], s2);
                g_S[(size_t)t * H_DIM + row] = s2;
            }
        }
        grid_bar(nb, barit);
    }
}

// ---------------- launch ----------------
extern "C" void kernel_launch(void* const* d_in, const int* in_sizes, int n_in,
                              void* d_out, int out_size)
{
    (void)n_in; (void)out_size;

    const float *actions, *state, *Wih, *Whh, *bih, *bhh;
    const float *fc1w, *fc1b, *fc2w, *fc2b, *meanw, *meanb, *stdw, *stdb;

    if (in_sizes[0] == T_STEPS * A_DIM) {
        // declaration order
        actions = (const float*)d_in[0];  state = (const float*)d_in[1];
        Wih     = (const float*)d_in[2];  Whh   = (const float*)d_in[3];
        bih     = (const float*)d_in[4];  bhh   = (const float*)d_in[5];
        fc1w    = (const float*)d_in[6];  fc1b  = (const float*)d_in[7];
        fc2w    = (const float*)d_in[8];  fc2b  = (const float*)d_in[9];
        meanw   = (const float*)d_in[10]; meanb = (const float*)d_in[11];
        stdw    = (const float*)d_in[12]; stdb  = (const float*)d_in[13];
    } else {
        // alphabetical: W_hh, W_ih, actions, b_hh, b_ih, fc1_b, fc1_w, fc2_b,
        //               fc2_w, mean_b, mean_w, state, std_b, std_w
        Whh     = (const float*)d_in[0];  Wih   = (const float*)d_in[1];
        actions = (const float*)d_in[2];  bhh   = (const float*)d_in[3];
        bih     = (const float*)d_in[4];  fc1b  = (const float*)d_in[5];
        fc1w    = (const float*)d_in[6];  fc2b  = (const float*)d_in[7];
        fc2w    = (const float*)d_in[8];  meanb = (const float*)d_in[9];
        meanw   = (const float*)d_in[10]; state = (const float*)d_in[11];
        stdb    = (const float*)d_in[12]; stdw  = (const float*)d_in[13];
    }
    float* out = (float*)d_out;

    int dev = 0;
    cudaGetDevice(&dev);
    int nsm = 148;
    cudaDeviceGetAttribute(&nsm, cudaDevAttrMultiProcessorCount, dev);
    if (nsm < 128) nsm = 128;         // mapping needs 16*NB >= 2048

    float*  gi = nullptr;  cudaGetSymbolAddress((void**)&gi,  g_GI);
    float*  S  = nullptr;  cudaGetSymbolAddress((void**)&S,   g_S);
    __half* wh = nullptr;  cudaGetSymbolAddress((void**)&wh,  g_whh_h);
    __half* f1 = nullptr;  cudaGetSymbolAddress((void**)&f1,  g_fc1_h);
    __half* f2 = nullptr;  cudaGetSymbolAddress((void**)&f2,  g_fc2_h);

    // 1) reset barrier + initial state (every replay)
    reset_kernel<<<2, 1024>>>(state);

    // 2) convert recurrent weights to fp16 (every replay; deterministic)
    convert_h_kernel<<<1184, 256>>>(Whh,  wh, G3 * H_DIM);
    convert_h_kernel<<<512,  256>>>(fc1w, f1, H_DIM * H_DIM);
    convert_h_kernel<<<512,  256>>>(fc2w, f2, H_DIM * H_DIM);

    // 3) precompute input gates: GI[t][g] = actions[t] . W_ih[g] + b_ih[g]
    {
        dim3 grid(G3 / 64, T_STEPS / 64);
        gemm_bias_act<<<grid, 256>>>(actions, Wih, bih, gi, T_STEPS, G3, A_DIM, 0);
    }

    // 4) sequential recurrence (persistent, grid-barrier synced)
    recurrent_kernel<<<nsm, 512>>>(bhh, fc1b, fc2b, nsm);

    // 5) deferred heads: means (identity) and stds (softplus)
    {
        dim3 grid(H_DIM / 64, T_STEPS / 64);
        gemm_bias_act<<<grid, 256>>>(S, meanw, meanb, out, T_STEPS, H_DIM, H_DIM, 0);
        gemm_bias_act<<<grid, 256>>>(S, stdw,  stdb,  out + (size_t)T_STEPS * H_DIM,
                                     T_STEPS, H_DIM, H_DIM, 1);
    }
}

// round 10
// speedup vs baseline: 1.3714x; 1.0771x over previous
#include <cuda_runtime.h>
#include <cuda_fp16.h>
#include <cstdint>
#include <math.h>

#define T_STEPS 1024
#define A_DIM   64
#define H_DIM   2048
#define G3      (3 * H_DIM)
#define WSLOTS  16                       // per-CTA warp slots for GRU weights in SMEM
#define SMV_BYTES (H_DIM * 4)            // staged fp32 vector
#define DSM_BYTES (SMV_BYTES + WSLOTS * 3 * H_DIM * 2)   // 8192 + 196608 = 204800

// ---------------- persistent device scratch (no allocations allowed) ----------------
__device__ float    g_GI[T_STEPS * G3];       // precomputed input gates (incl. b_ih)
__device__ float    g_S [T_STEPS * H_DIM];    // s2 per step for deferred mean/std GEMMs
__device__ float    g_h [H_DIM];              // carried state (= previous s2)
__device__ float    g_s0[H_DIM];
__device__ float    g_s1[H_DIM];
__device__ unsigned g_barcnt;                 // monotonic grid barrier counter

// ---------------- helpers ----------------
__device__ __forceinline__ float sigmoidf_(float x) { return 1.0f / (1.0f + expf(-x)); }
__device__ __forceinline__ float eluf_(float x)     { return x > 0.0f ? x : expm1f(x); }

__device__ __forceinline__ uint4 pack8h(float4 a, float4 b)
{
    __half2 h0 = __floats2half2_rn(a.x, a.y);
    __half2 h1 = __floats2half2_rn(a.z, a.w);
    __half2 h2 = __floats2half2_rn(b.x, b.y);
    __half2 h3 = __floats2half2_rn(b.z, b.w);
    uint4 u;
    u.x = *reinterpret_cast<uint32_t*>(&h0);
    u.y = *reinterpret_cast<uint32_t*>(&h1);
    u.z = *reinterpret_cast<uint32_t*>(&h2);
    u.w = *reinterpret_cast<uint32_t*>(&h3);
    return u;
}

// dot of 8 packed fp16 weights with 8 fp32 values
__device__ __forceinline__ float dot8(uint4 u, float4 s0, float4 s1)
{
    const __half2* h2 = reinterpret_cast<const __half2*>(&u);
    float2 f0 = __half22float2(h2[0]);
    float2 f1 = __half22float2(h2[1]);
    float2 f2 = __half22float2(h2[2]);
    float2 f3 = __half22float2(h2[3]);
    return f0.x*s0.x + f0.y*s0.y + f1.x*s0.z + f1.y*s0.w
         + f2.x*s1.x + f2.y*s1.y + f3.x*s1.z + f3.y*s1.w;
}

// Grid-wide barrier: monotonic counter, all NB blocks co-resident (1 CTA/SM).
__device__ __forceinline__ void grid_bar(unsigned nb, unsigned& it)
{
    __threadfence();
    __syncthreads();
    it += 1;
    if (threadIdx.x == 0) {
        atomicAdd(&g_barcnt, 1u);
        const unsigned tgt = it * nb;
        volatile unsigned* p = &g_barcnt;
        while (*p < tgt) { }
        __threadfence();
    }
    __syncthreads();
}

// ---------------- init kernel (each replay: resets barrier + state) ------
__global__ void reset_kernel(const float* __restrict__ state)
{
    int i = blockIdx.x * blockDim.x + threadIdx.x;
    if (i < H_DIM) g_h[i] = state[i];
    if (i == 0)    g_barcnt = 0u;
}

// ---------------- generic C[m][n] = act( sum_k A[m][k]*B[n][k] + bias[n] ) ----------
__global__ void __launch_bounds__(256) gemm_bias_act(
    const float* __restrict__ A, const float* __restrict__ B,
    const float* __restrict__ bias, float* __restrict__ C,
    int M, int N, int K, int act)
{
    __shared__ __align__(16) float As[16][68];
    __shared__ __align__(16) float Bs[16][68];

    const int tid = threadIdx.x;
    const int tx  = tid & 15;
    const int ty  = tid >> 4;
    const int n0  = blockIdx.x * 64;
    const int m0  = blockIdx.y * 64;

    float c[4][4] = {};

    for (int k0 = 0; k0 < K; k0 += 16) {
        #pragma unroll
        for (int idx = tid; idx < 64 * 16; idx += 256) {
            int m  = idx >> 4;
            int kk = idx & 15;
            As[kk][m] = A[(size_t)(m0 + m) * K + k0 + kk];
            Bs[kk][m] = B[(size_t)(n0 + m) * K + k0 + kk];
        }
        __syncthreads();

        #pragma unroll
        for (int kk = 0; kk < 16; ++kk) {
            float4 a4 = *reinterpret_cast<const float4*>(&As[kk][ty * 4]);
            float4 b4 = *reinterpret_cast<const float4*>(&Bs[kk][tx * 4]);
            c[0][0] += a4.x * b4.x; c[0][1] += a4.x * b4.y; c[0][2] += a4.x * b4.z; c[0][3] += a4.x * b4.w;
            c[1][0] += a4.y * b4.x; c[1][1] += a4.y * b4.y; c[1][2] += a4.y * b4.z; c[1][3] += a4.y * b4.w;
            c[2][0] += a4.z * b4.x; c[2][1] += a4.z * b4.y; c[2][2] += a4.z * b4.z; c[2][3] += a4.z * b4.w;
            c[3][0] += a4.w * b4.x; c[3][1] += a4.w * b4.y; c[3][2] += a4.w * b4.z; c[3][3] += a4.w * b4.w;
        }
        __syncthreads();
    }

    #pragma unroll
    for (int i = 0; i < 4; ++i) {
        #pragma unroll
        for (int j = 0; j < 4; ++j) {
            int m = m0 + ty * 4 + i;
            int n = n0 + tx * 4 + j;
            float v = c[i][j] + bias[n];
            if (act == 1) v = (v > 20.0f) ? v : log1pf(expf(v));   // softplus
            C[(size_t)m * N + n] = v;
        }
    }
}

// ---------------- persistent recurrent kernel: SM-resident weights ----------------
// grid = NB (= #SMs), 512 threads, 1 CTA/SM (204.8 KB dynamic SMEM forces it).
// GRU weights live in SMEM (fp16, per-warp slot); fc1/fc2 rows live in registers.
// The t-loop therefore reads NO weights from L2/DRAM.
__global__ void __launch_bounds__(512, 1) recurrent_kernel(
    const float* __restrict__ Whh,  const float* __restrict__ bhh,
    const float* __restrict__ fc1w, const float* __restrict__ fc1b,
    const float* __restrict__ fc2w, const float* __restrict__ fc2b,
    int NB)
{
    extern __shared__ __align__(16) char dsm[];
    float*  smv = reinterpret_cast<float*>(dsm);                 // [2048] staged vector
    __half* wg  = reinterpret_cast<__half*>(dsm + SMV_BYTES);    // [WSLOTS][3][2048]

    const int tid  = threadIdx.x;
    const int bid  = blockIdx.x;
    const int wid  = tid >> 5;
    const int lane = tid & 31;
    const unsigned nb = (unsigned)NB;
    unsigned barit = 0;

    const int  row  = wid * NB + bid;      // this warp's output row in every phase
    const bool live = (row < H_DIM);
    const int  kb   = lane * 8;            // per-lane K base (8 elements / uint4)

    __half* wrow = wg + (size_t)wid * 3 * H_DIM;

    // ---------- one-time: weights -> SMEM (GRU) and registers (fc1, fc2) ----------
    uint4 rf1[8], rf2[8];
    if (live) {
        #pragma unroll
        for (int g = 0; g < 3; ++g) {
            const float* src = Whh + (size_t)(row + g * H_DIM) * H_DIM;
            #pragma unroll
            for (int it = 0; it < 8; ++it) {
                const int k = kb + it * 256;
                float4 a = *reinterpret_cast<const float4*>(src + k);
                float4 b = *reinterpret_cast<const float4*>(src + k + 4);
                *reinterpret_cast<uint4*>(wrow + g * H_DIM + k) = pack8h(a, b);
            }
        }
        const float* s1p = fc1w + (size_t)row * H_DIM;
        const float* s2p = fc2w + (size_t)row * H_DIM;
        #pragma unroll
        for (int it = 0; it < 8; ++it) {
            const int k = kb + it * 256;
            float4 a1 = *reinterpret_cast<const float4*>(s1p + k);
            float4 b1 = *reinterpret_cast<const float4*>(s1p + k + 4);
            float4 a2 = *reinterpret_cast<const float4*>(s2p + k);
            float4 b2 = *reinterpret_cast<const float4*>(s2p + k + 4);
            rf1[it] = pack8h(a1, b1);
            rf2[it] = pack8h(a2, b2);
        }
    } else {
        #pragma unroll
        for (int it = 0; it < 8; ++it) { rf1[it] = make_uint4(0,0,0,0); rf2[it] = make_uint4(0,0,0,0); }
    }
    // (each warp reads only its own SMEM slot; no block sync needed for weights)

    for (int t = 0; t < T_STEPS; ++t) {
        // ---------- stage h into smem ----------
        {
            float4 v = __ldcg(reinterpret_cast<const float4*>(g_h + tid * 4));
            *reinterpret_cast<float4*>(smv + tid * 4) = v;
        }
        __syncthreads();

        // ---------- P1: GRU cell (weights from SMEM) ----------
        if (live) {
            float a0 = 0.f, a1 = 0.f, a2 = 0.f;
            #pragma unroll 2
            for (int it = 0; it < 8; ++it) {
                const int k = kb + it * 256;
                float4 s0 = *reinterpret_cast<const float4*>(smv + k);
                float4 s1 = *reinterpret_cast<const float4*>(smv + k + 4);
                uint4 u0 = *reinterpret_cast<const uint4*>(wrow + k);
                uint4 u1 = *reinterpret_cast<const uint4*>(wrow + H_DIM + k);
                uint4 u2 = *reinterpret_cast<const uint4*>(wrow + 2 * H_DIM + k);
                a0 += dot8(u0, s0, s1);
                a1 += dot8(u1, s0, s1);
                a2 += dot8(u2, s0, s1);
            }
            #pragma unroll
            for (int o = 16; o > 0; o >>= 1) {
                a0 += __shfl_xor_sync(0xffffffffu, a0, o);
                a1 += __shfl_xor_sync(0xffffffffu, a1, o);
                a2 += __shfl_xor_sync(0xffffffffu, a2, o);
            }
            if (lane == 0) {
                const float* gi = g_GI + (size_t)t * G3;
                float ir = gi[row], iz = gi[row + H_DIM], in_ = gi[row + 2 * H_DIM];
                float hr = a0 + bhh[row];
                float hz = a1 + bhh[row + H_DIM];
                float hn = a2 + bhh[row + 2 * H_DIM];
                float r  = sigmoidf_(ir + hr);
                float z  = sigmoidf_(iz + hz);
                float n  = tanhf(in_ + r * hn);
                float hp = smv[row];
                float hnew = (1.0f - z) * n + z * hp;
                __stcg(&g_s0[row], eluf_(hnew));
            }
        }
        grid_bar(nb, barit);

        // ---------- stage s0 ----------
        {
            float4 v = __ldcg(reinterpret_cast<const float4*>(g_s0 + tid * 4));
            *reinterpret_cast<float4*>(smv + tid * 4) = v;
        }
        __syncthreads();

        // ---------- P2: fc1 (weights from registers) ----------
        if (live) {
            float a = 0.f;
            #pragma unroll
            for (int it = 0; it < 8; ++it) {
                const int k = kb + it * 256;
                float4 s0 = *reinterpret_cast<const float4*>(smv + k);
                float4 s1 = *reinterpret_cast<const float4*>(smv + k + 4);
                a += dot8(rf1[it], s0, s1);
            }
            #pragma unroll
            for (int o = 16; o > 0; o >>= 1) a += __shfl_xor_sync(0xffffffffu, a, o);
            if (lane == 0) __stcg(&g_s1[row], eluf_(a + fc1b[row]));
        }
        grid_bar(nb, barit);

        // ---------- stage s1 ----------
        {
            float4 v = __ldcg(reinterpret_cast<const float4*>(g_s1 + tid * 4));
            *reinterpret_cast<float4*>(smv + tid * 4) = v;
        }
        __syncthreads();

        // ---------- P3: fc2 (weights from registers; result is next h and S[t]) ----------
        if (live) {
            float a = 0.f;
            #pragma unroll
            for (int it = 0; it < 8; ++it) {
                const int k = kb + it * 256;
                float4 s0 = *reinterpret_cast<const float4*>(smv + k);
                float4 s1 = *reinterpret_cast<const float4*>(smv + k + 4);
                a += dot8(rf2[it], s0, s1);
            }
            #pragma unroll
            for (int o = 16; o > 0; o >>= 1) a += __shfl_xor_sync(0xffffffffu, a, o);
            if (lane == 0) {
                float s2 = eluf_(a + fc2b[row]);
                __stcg(&g_h[row], s2);
                g_S[(size_t)t * H_DIM + row] = s2;
            }
        }
        grid_bar(nb, barit);
    }
}

// ---------------- launch ----------------
extern "C" void kernel_launch(void* const* d_in, const int* in_sizes, int n_in,
                              void* d_out, int out_size)
{
    (void)n_in; (void)out_size;

    const float *actions, *state, *Wih, *Whh, *bih, *bhh;
    const float *fc1w, *fc1b, *fc2w, *fc2b, *meanw, *meanb, *stdw, *stdb;

    if (in_sizes[0] == T_STEPS * A_DIM) {
        // declaration order
        actions = (const float*)d_in[0];  state = (const float*)d_in[1];
        Wih     = (const float*)d_in[2];  Whh   = (const float*)d_in[3];
        bih     = (const float*)d_in[4];  bhh   = (const float*)d_in[5];
        fc1w    = (const float*)d_in[6];  fc1b  = (const float*)d_in[7];
        fc2w    = (const float*)d_in[8];  fc2b  = (const float*)d_in[9];
        meanw   = (const float*)d_in[10]; meanb = (const float*)d_in[11];
        stdw    = (const float*)d_in[12]; stdb  = (const float*)d_in[13];
    } else {
        // alphabetical: W_hh, W_ih, actions, b_hh, b_ih, fc1_b, fc1_w, fc2_b,
        //               fc2_w, mean_b, mean_w, state, std_b, std_w
        Whh     = (const float*)d_in[0];  Wih   = (const float*)d_in[1];
        actions = (const float*)d_in[2];  bhh   = (const float*)d_in[3];
        bih     = (const float*)d_in[4];  fc1b  = (const float*)d_in[5];
        fc1w    = (const float*)d_in[6];  fc2b  = (const float*)d_in[7];
        fc2w    = (const float*)d_in[8];  meanb = (const float*)d_in[9];
        meanw   = (const float*)d_in[10]; state = (const float*)d_in[11];
        stdb    = (const float*)d_in[12]; stdw  = (const float*)d_in[13];
    }
    float* out = (float*)d_out;

    int dev = 0;
    cudaGetDevice(&dev);
    int nsm = 148;
    cudaDeviceGetAttribute(&nsm, cudaDevAttrMultiProcessorCount, dev);
    if (nsm < 128) nsm = 128;         // mapping needs 16*NB >= 2048

    float* gi = nullptr;  cudaGetSymbolAddress((void**)&gi, g_GI);
    float* S  = nullptr;  cudaGetSymbolAddress((void**)&S,  g_S);

    // allow 204.8 KB dynamic SMEM (idempotent; host-side attribute, not a stream op)
    static bool attr_done = false;
    if (!attr_done) {
        cudaFuncSetAttribute(recurrent_kernel,
                             cudaFuncAttributeMaxDynamicSharedMemorySize, DSM_BYTES);
        attr_done = true;
    }

    // 1) reset barrier + initial state (every replay)
    reset_kernel<<<2, 1024>>>(state);

    // 2) precompute input gates: GI[t][g] = actions[t] . W_ih[g] + b_ih[g]
    {
        dim3 grid(G3 / 64, T_STEPS / 64);
        gemm_bias_act<<<grid, 256>>>(actions, Wih, bih, gi, T_STEPS, G3, A_DIM, 0);
    }

    // 3) sequential recurrence (persistent, SM-resident weights)
    recurrent_kernel<<<nsm, 512, DSM_BYTES>>>(Whh, bhh, fc1w, fc1b, fc2w, fc2b, nsm);

    // 4) deferred heads: means (identity) and stds (softplus)
    {
        dim3 grid(H_DIM / 64, T_STEPS / 64);
        gemm_bias_act<<<grid, 256>>>(S, meanw, meanb, out, T_STEPS, H_DIM, H_DIM, 0);
        gemm_bias_act<<<grid, 256>>>(S, stdw,  stdb,  out + (size_t)T_STEPS * H_DIM,
                                     T_STEPS, H_DIM, H_DIM, 1);
    }
}

// round 12
// speedup vs baseline: 1.6307x; 1.1890x over previous
#include <cuda_runtime.h>
#include <cuda_fp16.h>
#include <cstdint>
#include <math.h>

#define T_STEPS 1024
#define A_DIM   64
#define H_DIM   2048
#define G3      (3 * H_DIM)
#define WSLOTS  16                       // per-CTA warp slots for GRU weights in SMEM
#define SMV_BYTES (H_DIM * 4)            // staged fp32 vector
#define DSM_BYTES (SMV_BYTES + WSLOTS * 3 * H_DIM * 2)   // 8192 + 196608 = 204800

// ---------------- persistent device scratch (no allocations allowed) ----------------
__device__ float    g_GI[T_STEPS * G3];       // precomputed input gates (incl. b_ih)
__device__ float    g_S [T_STEPS * H_DIM];    // s2 per step for deferred mean/std GEMMs
__device__ float    g_h [H_DIM];              // carried state (= previous s2)
__device__ float    g_s0[H_DIM];
__device__ float    g_s1[H_DIM];
__device__ unsigned g_barcnt;                 // monotonic grid barrier counter

// ---------------- helpers ----------------
__device__ __forceinline__ float sigmoidf_(float x) { return 1.0f / (1.0f + expf(-x)); }
__device__ __forceinline__ float eluf_(float x)     { return x > 0.0f ? x : expm1f(x); }

__device__ __forceinline__ uint4 pack8h(float4 a, float4 b)
{
    __half2 h0 = __floats2half2_rn(a.x, a.y);
    __half2 h1 = __floats2half2_rn(a.z, a.w);
    __half2 h2 = __floats2half2_rn(b.x, b.y);
    __half2 h3 = __floats2half2_rn(b.z, b.w);
    uint4 u;
    u.x = *reinterpret_cast<uint32_t*>(&h0);
    u.y = *reinterpret_cast<uint32_t*>(&h1);
    u.z = *reinterpret_cast<uint32_t*>(&h2);
    u.w = *reinterpret_cast<uint32_t*>(&h3);
    return u;
}

// dot of 8 packed fp16 weights with 8 fp32 values
__device__ __forceinline__ float dot8(uint4 u, float4 s0, float4 s1)
{
    const __half2* h2 = reinterpret_cast<const __half2*>(&u);
    float2 f0 = __half22float2(h2[0]);
    float2 f1 = __half22float2(h2[1]);
    float2 f2 = __half22float2(h2[2]);
    float2 f3 = __half22float2(h2[3]);
    return f0.x*s0.x + f0.y*s0.y + f1.x*s0.z + f1.y*s0.w
         + f2.x*s1.x + f2.y*s1.y + f3.x*s1.z + f3.y*s1.w;
}

// Grid-wide barrier via release-RED arrival + acquire-load spin.
// No membar.gl => no CCTL.IVALL L1 flush. Cumulativity: the leading
// __syncthreads puts every warp's prior __stcg stores into the release set of
// thread 0's red.release; consumer's ld.acquire + trailing __syncthreads
// propagates visibility to all threads (cooperative-groups grid.sync pattern).
__device__ __forceinline__ void grid_bar(unsigned nb, unsigned& it)
{
    __syncthreads();
    it += 1;
    if (threadIdx.x == 0) {
        asm volatile("red.release.gpu.global.add.u32 [%0], 1;"
                     :: "l"(&g_barcnt) : "memory");
        const unsigned tgt = it * nb;
        unsigned v;
        do {
            asm volatile("ld.acquire.gpu.global.u32 %0, [%1];"
                         : "=r"(v) : "l"(&g_barcnt) : "memory");
        } while (v < tgt);
    }
    __syncthreads();
}

// ---------------- init kernel (each replay: resets barrier + state) ------
__global__ void reset_kernel(const float* __restrict__ state)
{
    int i = blockIdx.x * blockDim.x + threadIdx.x;
    if (i < H_DIM) g_h[i] = state[i];
    if (i == 0)    g_barcnt = 0u;
}

// ---------------- generic C[m][n] = act( sum_k A[m][k]*B[n][k] + bias[n] ) ----------
__global__ void __launch_bounds__(256) gemm_bias_act(
    const float* __restrict__ A, const float* __restrict__ B,
    const float* __restrict__ bias, float* __restrict__ C,
    int M, int N, int K, int act)
{
    __shared__ __align__(16) float As[16][68];
    __shared__ __align__(16) float Bs[16][68];

    const int tid = threadIdx.x;
    const int tx  = tid & 15;
    const int ty  = tid >> 4;
    const int n0  = blockIdx.x * 64;
    const int m0  = blockIdx.y * 64;

    float c[4][4] = {};

    for (int k0 = 0; k0 < K; k0 += 16) {
        #pragma unroll
        for (int idx = tid; idx < 64 * 16; idx += 256) {
            int m  = idx >> 4;
            int kk = idx & 15;
            As[kk][m] = A[(size_t)(m0 + m) * K + k0 + kk];
            Bs[kk][m] = B[(size_t)(n0 + m) * K + k0 + kk];
        }
        __syncthreads();

        #pragma unroll
        for (int kk = 0; kk < 16; ++kk) {
            float4 a4 = *reinterpret_cast<const float4*>(&As[kk][ty * 4]);
            float4 b4 = *reinterpret_cast<const float4*>(&Bs[kk][tx * 4]);
            c[0][0] += a4.x * b4.x; c[0][1] += a4.x * b4.y; c[0][2] += a4.x * b4.z; c[0][3] += a4.x * b4.w;
            c[1][0] += a4.y * b4.x; c[1][1] += a4.y * b4.y; c[1][2] += a4.y * b4.z; c[1][3] += a4.y * b4.w;
            c[2][0] += a4.z * b4.x; c[2][1] += a4.z * b4.y; c[2][2] += a4.z * b4.z; c[2][3] += a4.z * b4.w;
            c[3][0] += a4.w * b4.x; c[3][1] += a4.w * b4.y; c[3][2] += a4.w * b4.z; c[3][3] += a4.w * b4.w;
        }
        __syncthreads();
    }

    #pragma unroll
    for (int i = 0; i < 4; ++i) {
        #pragma unroll
        for (int j = 0; j < 4; ++j) {
            int m = m0 + ty * 4 + i;
            int n = n0 + tx * 4 + j;
            float v = c[i][j] + bias[n];
            if (act == 1) v = (v > 20.0f) ? v : log1pf(expf(v));   // softplus
            C[(size_t)m * N + n] = v;
        }
    }
}

// ---------------- persistent recurrent kernel: SM-resident weights ----------------
// grid = NB (= #SMs), 512 threads, 1 CTA/SM (204.8 KB dynamic SMEM forces it).
// GRU weights in SMEM (fp16, per-warp slot); fc1/fc2 rows in registers.
// Loop reads no weights from L2/DRAM; biases hoisted; GI prefetched per phase.
__global__ void __launch_bounds__(512, 1) recurrent_kernel(
    const float* __restrict__ Whh,  const float* __restrict__ bhh,
    const float* __restrict__ fc1w, const float* __restrict__ fc1b,
    const float* __restrict__ fc2w, const float* __restrict__ fc2b,
    int NB)
{
    extern __shared__ __align__(16) char dsm[];
    float*  smv = reinterpret_cast<float*>(dsm);                 // [2048] staged vector
    __half* wg  = reinterpret_cast<__half*>(dsm + SMV_BYTES);    // [WSLOTS][3][2048]

    const int tid  = threadIdx.x;
    const int bid  = blockIdx.x;
    const int wid  = tid >> 5;
    const int lane = tid & 31;
    const unsigned nb = (unsigned)NB;
    unsigned barit = 0;

    const int  row  = wid * NB + bid;      // this warp's output row in every phase
    const bool live = (row < H_DIM);
    const int  kb   = lane * 8;            // per-lane K base (8 elements / uint4)

    __half* wrow = wg + (size_t)wid * 3 * H_DIM;

    // ---------- one-time: weights -> SMEM (GRU) and registers (fc1, fc2) ----------
    uint4 rf1[8], rf2[8];
    float b_r = 0.f, b_z = 0.f, b_n = 0.f, b_f1 = 0.f, b_f2 = 0.f;   // hoisted biases
    if (live) {
        #pragma unroll
        for (int g = 0; g < 3; ++g) {
            const float* src = Whh + (size_t)(row + g * H_DIM) * H_DIM;
            #pragma unroll
            for (int it = 0; it < 8; ++it) {
                const int k = kb + it * 256;
                float4 a = *reinterpret_cast<const float4*>(src + k);
                float4 b = *reinterpret_cast<const float4*>(src + k + 4);
                *reinterpret_cast<uint4*>(wrow + g * H_DIM + k) = pack8h(a, b);
            }
        }
        const float* s1p = fc1w + (size_t)row * H_DIM;
        const float* s2p = fc2w + (size_t)row * H_DIM;
        #pragma unroll
        for (int it = 0; it < 8; ++it) {
            const int k = kb + it * 256;
            float4 a1 = *reinterpret_cast<const float4*>(s1p + k);
            float4 b1 = *reinterpret_cast<const float4*>(s1p + k + 4);
            float4 a2 = *reinterpret_cast<const float4*>(s2p + k);
            float4 b2 = *reinterpret_cast<const float4*>(s2p + k + 4);
            rf1[it] = pack8h(a1, b1);
            rf2[it] = pack8h(a2, b2);
        }
        b_r  = bhh[row];
        b_z  = bhh[row + H_DIM];
        b_n  = bhh[row + 2 * H_DIM];
        b_f1 = fc1b[row];
        b_f2 = fc2b[row];
    } else {
        #pragma unroll
        for (int it = 0; it < 8; ++it) { rf1[it] = make_uint4(0,0,0,0); rf2[it] = make_uint4(0,0,0,0); }
    }
    // (each warp reads only its own SMEM slot; no block sync needed for weights)

    for (int t = 0; t < T_STEPS; ++t) {
        // ---------- stage h into smem ----------
        {
            float4 v = __ldcg(reinterpret_cast<const float4*>(g_h + tid * 4));
            *reinterpret_cast<float4*>(smv + tid * 4) = v;
        }
        __syncthreads();

        // ---------- P1: GRU cell (weights from SMEM) ----------
        if (live) {
            // prefetch GI[t] early so L2 latency overlaps the dot product
            float ir = 0.f, iz = 0.f, in_ = 0.f;
            if (lane == 0) {
                const float* gi = g_GI + (size_t)t * G3;
                ir  = __ldcg(gi + row);
                iz  = __ldcg(gi + row + H_DIM);
                in_ = __ldcg(gi + row + 2 * H_DIM);
            }
            float a0 = 0.f, a1 = 0.f, a2 = 0.f;
            #pragma unroll 2
            for (int it = 0; it < 8; ++it) {
                const int k = kb + it * 256;
                float4 s0 = *reinterpret_cast<const float4*>(smv + k);
                float4 s1 = *reinterpret_cast<const float4*>(smv + k + 4);
                uint4 u0 = *reinterpret_cast<const uint4*>(wrow + k);
                uint4 u1 = *reinterpret_cast<const uint4*>(wrow + H_DIM + k);
                uint4 u2 = *reinterpret_cast<const uint4*>(wrow + 2 * H_DIM + k);
                a0 += dot8(u0, s0, s1);
                a1 += dot8(u1, s0, s1);
                a2 += dot8(u2, s0, s1);
            }
            #pragma unroll
            for (int o = 16; o > 0; o >>= 1) {
                a0 += __shfl_xor_sync(0xffffffffu, a0, o);
                a1 += __shfl_xor_sync(0xffffffffu, a1, o);
                a2 += __shfl_xor_sync(0xffffffffu, a2, o);
            }
            if (lane == 0) {
                float r  = sigmoidf_(ir + a0 + b_r);
                float z  = sigmoidf_(iz + a1 + b_z);
                float n  = tanhf(in_ + r * (a2 + b_n));
                float hp = smv[row];
                float hnew = (1.0f - z) * n + z * hp;
                __stcg(&g_s0[row], eluf_(hnew));
            }
        }
        grid_bar(nb, barit);

        // ---------- stage s0 ----------
        {
            float4 v = __ldcg(reinterpret_cast<const float4*>(g_s0 + tid * 4));
            *reinterpret_cast<float4*>(smv + tid * 4) = v;
        }
        __syncthreads();

        // ---------- P2: fc1 (weights from registers) ----------
        if (live) {
            float a = 0.f;
            #pragma unroll
            for (int it = 0; it < 8; ++it) {
                const int k = kb + it * 256;
                float4 s0 = *reinterpret_cast<const float4*>(smv + k);
                float4 s1 = *reinterpret_cast<const float4*>(smv + k + 4);
                a += dot8(rf1[it], s0, s1);
            }
            #pragma unroll
            for (int o = 16; o > 0; o >>= 1) a += __shfl_xor_sync(0xffffffffu, a, o);
            if (lane == 0) __stcg(&g_s1[row], eluf_(a + b_f1));
        }
        grid_bar(nb, barit);

        // ---------- stage s1 ----------
        {
            float4 v = __ldcg(reinterpret_cast<const float4*>(g_s1 + tid * 4));
            *reinterpret_cast<float4*>(smv + tid * 4) = v;
        }
        __syncthreads();

        // ---------- P3: fc2 (weights from registers; result is next h and S[t]) ----------
        if (live) {
            float a = 0.f;
            #pragma unroll
            for (int it = 0; it < 8; ++it) {
                const int k = kb + it * 256;
                float4 s0 = *reinterpret_cast<const float4*>(smv + k);
                float4 s1 = *reinterpret_cast<const float4*>(smv + k + 4);
                a += dot8(rf2[it], s0, s1);
            }
            #pragma unroll
            for (int o = 16; o > 0; o >>= 1) a += __shfl_xor_sync(0xffffffffu, a, o);
            if (lane == 0) {
                float s2 = eluf_(a + b_f2);
                __stcg(&g_h[row], s2);
                g_S[(size_t)t * H_DIM + row] = s2;
            }
        }
        grid_bar(nb, barit);
    }
}

// ---------------- launch ----------------
extern "C" void kernel_launch(void* const* d_in, const int* in_sizes, int n_in,
                              void* d_out, int out_size)
{
    (void)n_in; (void)out_size;

    const float *actions, *state, *Wih, *Whh, *bih, *bhh;
    const float *fc1w, *fc1b, *fc2w, *fc2b, *meanw, *meanb, *stdw, *stdb;

    if (in_sizes[0] == T_STEPS * A_DIM) {
        // declaration order
        actions = (const float*)d_in[0];  state = (const float*)d_in[1];
        Wih     = (const float*)d_in[2];  Whh   = (const float*)d_in[3];
        bih     = (const float*)d_in[4];  bhh   = (const float*)d_in[5];
        fc1w    = (const float*)d_in[6];  fc1b  = (const float*)d_in[7];
        fc2w    = (const float*)d_in[8];  fc2b  = (const float*)d_in[9];
        meanw   = (const float*)d_in[10]; meanb = (const float*)d_in[11];
        stdw    = (const float*)d_in[12]; stdb  = (const float*)d_in[13];
    } else {
        // alphabetical: W_hh, W_ih, actions, b_hh, b_ih, fc1_b, fc1_w, fc2_b,
        //               fc2_w, mean_b, mean_w, state, std_b, std_w
        Whh     = (const float*)d_in[0];  Wih   = (const float*)d_in[1];
        actions = (const float*)d_in[2];  bhh   = (const float*)d_in[3];
        bih     = (const float*)d_in[4];  fc1b  = (const float*)d_in[5];
        fc1w    = (const float*)d_in[6];  fc2b  = (const float*)d_in[7];
        fc2w    = (const float*)d_in[8];  meanb = (const float*)d_in[9];
        meanw   = (const float*)d_in[10]; state = (const float*)d_in[11];
        stdb    = (const float*)d_in[12]; stdw  = (const float*)d_in[13];
    }
    float* out = (float*)d_out;

    int dev = 0;
    cudaGetDevice(&dev);
    int nsm = 148;
    cudaDeviceGetAttribute(&nsm, cudaDevAttrMultiProcessorCount, dev);
    if (nsm < 128) nsm = 128;         // mapping needs 16*NB >= 2048

    float* gi = nullptr;  cudaGetSymbolAddress((void**)&gi, g_GI);
    float* S  = nullptr;  cudaGetSymbolAddress((void**)&S,  g_S);

    // allow 204.8 KB dynamic SMEM (idempotent; host-side attribute, not a stream op)
    static bool attr_done = false;
    if (!attr_done) {
        cudaFuncSetAttribute(recurrent_kernel,
                             cudaFuncAttributeMaxDynamicSharedMemorySize, DSM_BYTES);
        attr_done = true;
    }

    // 1) reset barrier + initial state (every replay)
    reset_kernel<<<2, 1024>>>(state);

    // 2) precompute input gates: GI[t][g] = actions[t] . W_ih[g] + b_ih[g]
    {
        dim3 grid(G3 / 64, T_STEPS / 64);
        gemm_bias_act<<<grid, 256>>>(actions, Wih, bih, gi, T_STEPS, G3, A_DIM, 0);
    }

    // 3) sequential recurrence (persistent, SM-resident weights)
    recurrent_kernel<<<nsm, 512, DSM_BYTES>>>(Whh, bhh, fc1w, fc1b, fc2w, fc2b, nsm);

    // 4) deferred heads: means (identity) and stds (softplus)
    {
        dim3 grid(H_DIM / 64, T_STEPS / 64);
        gemm_bias_act<<<grid, 256>>>(S, meanw, meanb, out, T_STEPS, H_DIM, H_DIM, 0);
        gemm_bias_act<<<grid, 256>>>(S, stdw,  stdb,  out + (size_t)T_STEPS * H_DIM,
                                     T_STEPS, H_DIM, H_DIM, 1);
    }
}

// round 13
// speedup vs baseline: 1.6532x; 1.0138x over previous
#include <cuda_runtime.h>
#include <cuda_fp16.h>
#include <cstdint>
#include <math.h>

#define T_STEPS 1024
#define A_DIM   64
#define H_DIM   2048
#define G3      (3 * H_DIM)
#define WSLOTS  16                       // per-CTA warp slots for GRU weights in SMEM
#define SMV_BYTES (H_DIM * 4)            // staged fp32 vector
#define DSM_BYTES (SMV_BYTES + WSLOTS * 3 * H_DIM * 2)   // 8192 + 196608 = 204800

// ---------------- persistent device scratch (no allocations allowed) ----------------
__device__ float    g_GI[T_STEPS * G3];       // precomputed input gates (incl. b_ih)
__device__ float    g_S [T_STEPS * H_DIM];    // s2 per step for deferred mean/std GEMMs
__device__ float    g_h [H_DIM];              // carried state (= previous s2)
__device__ float    g_s0[H_DIM];
__device__ float    g_s1[H_DIM];
__device__ unsigned g_barcnt;                 // monotonic grid barrier counter

// ---------------- helpers ----------------
__device__ __forceinline__ float sigmoidf_(float x) { return 1.0f / (1.0f + expf(-x)); }
__device__ __forceinline__ float eluf_(float x)     { return x > 0.0f ? x : expm1f(x); }

__device__ __forceinline__ uint4 pack8h(float4 a, float4 b)
{
    __half2 h0 = __floats2half2_rn(a.x, a.y);
    __half2 h1 = __floats2half2_rn(a.z, a.w);
    __half2 h2 = __floats2half2_rn(b.x, b.y);
    __half2 h3 = __floats2half2_rn(b.z, b.w);
    uint4 u;
    u.x = *reinterpret_cast<uint32_t*>(&h0);
    u.y = *reinterpret_cast<uint32_t*>(&h1);
    u.z = *reinterpret_cast<uint32_t*>(&h2);
    u.w = *reinterpret_cast<uint32_t*>(&h3);
    return u;
}

// dot of 8 packed fp16 weights with 8 fp32 values
__device__ __forceinline__ float dot8(uint4 u, float4 s0, float4 s1)
{
    const __half2* h2 = reinterpret_cast<const __half2*>(&u);
    float2 f0 = __half22float2(h2[0]);
    float2 f1 = __half22float2(h2[1]);
    float2 f2 = __half22float2(h2[2]);
    float2 f3 = __half22float2(h2[3]);
    return f0.x*s0.x + f0.y*s0.y + f1.x*s0.z + f1.y*s0.w
         + f2.x*s1.x + f2.y*s1.y + f3.x*s1.z + f3.y*s1.w;
}

// Grid-wide barrier: release-RED arrival; relaxed poll with nanosleep backoff
// (keeps the counter's L2 line free so late arrivals' REDs aren't queued behind
// poll traffic); one acquire load on exit establishes ordering. No gpu-scope
// fence anywhere => no CCTL.IVALL L1 flush.
__device__ __forceinline__ void grid_bar(unsigned nb, unsigned& it)
{
    __syncthreads();
    it += 1;
    if (threadIdx.x == 0) {
        asm volatile("red.release.gpu.global.add.u32 [%0], 1;"
                     :: "l"(&g_barcnt) : "memory");
        const unsigned tgt = it * nb;
        unsigned v;
        asm volatile("ld.relaxed.gpu.global.u32 %0, [%1];"
                     : "=r"(v) : "l"(&g_barcnt) : "memory");
        while (v < tgt) {
            __nanosleep(64);
            asm volatile("ld.relaxed.gpu.global.u32 %0, [%1];"
                         : "=r"(v) : "l"(&g_barcnt) : "memory");
        }
        asm volatile("ld.acquire.gpu.global.u32 %0, [%1];"
                     : "=r"(v) : "l"(&g_barcnt) : "memory");
    }
    __syncthreads();
}

// ---------------- init kernel (each replay: resets barrier + state) ------
__global__ void reset_kernel(const float* __restrict__ state)
{
    int i = blockIdx.x * blockDim.x + threadIdx.x;
    if (i < H_DIM) g_h[i] = state[i];
    if (i == 0)    g_barcnt = 0u;
}

// ---------------- C[m][n] = act( sum_k A[m][k]*B[n][k] + bias[n] ) ----------
// BM=128, BN=64, BK=16, 256 threads, 8x4 micro-tile. All dims divide evenly.
__global__ void __launch_bounds__(256) gemm_bias_act(
    const float* __restrict__ A, const float* __restrict__ B,
    const float* __restrict__ bias, float* __restrict__ C,
    int M, int N, int K, int act)
{
    __shared__ __align__(16) float As[16][132];   // 128 + 4 pad (16B-aligned rows)
    __shared__ __align__(16) float Bs[16][68];

    const int tid = threadIdx.x;
    const int tx  = tid & 15;          // n micro index (4 cols)
    const int ty  = tid >> 4;          // m micro index (8 rows)
    const int n0  = blockIdx.x * 64;
    const int m0  = blockIdx.y * 128;

    float c[8][4] = {};

    for (int k0 = 0; k0 < K; k0 += 16) {
        #pragma unroll
        for (int idx = tid; idx < 128 * 16; idx += 256) {
            int m  = idx >> 4;
            int kk = idx & 15;
            As[kk][m] = A[(size_t)(m0 + m) * K + k0 + kk];
        }
        #pragma unroll
        for (int idx = tid; idx < 64 * 16; idx += 256) {
            int m  = idx >> 4;
            int kk = idx & 15;
            Bs[kk][m] = B[(size_t)(n0 + m) * K + k0 + kk];
        }
        __syncthreads();

        #pragma unroll
        for (int kk = 0; kk < 16; ++kk) {
            float4 b4 = *reinterpret_cast<const float4*>(&Bs[kk][tx * 4]);
            float4 a0 = *reinterpret_cast<const float4*>(&As[kk][ty * 8]);
            float4 a1 = *reinterpret_cast<const float4*>(&As[kk][ty * 8 + 4]);
            c[0][0] += a0.x * b4.x; c[0][1] += a0.x * b4.y; c[0][2] += a0.x * b4.z; c[0][3] += a0.x * b4.w;
            c[1][0] += a0.y * b4.x; c[1][1] += a0.y * b4.y; c[1][2] += a0.y * b4.z; c[1][3] += a0.y * b4.w;
            c[2][0] += a0.z * b4.x; c[2][1] += a0.z * b4.y; c[2][2] += a0.z * b4.z; c[2][3] += a0.z * b4.w;
            c[3][0] += a0.w * b4.x; c[3][1] += a0.w * b4.y; c[3][2] += a0.w * b4.z; c[3][3] += a0.w * b4.w;
            c[4][0] += a1.x * b4.x; c[4][1] += a1.x * b4.y; c[4][2] += a1.x * b4.z; c[4][3] += a1.x * b4.w;
            c[5][0] += a1.y * b4.x; c[5][1] += a1.y * b4.y; c[5][2] += a1.y * b4.z; c[5][3] += a1.y * b4.w;
            c[6][0] += a1.z * b4.x; c[6][1] += a1.z * b4.y; c[6][2] += a1.z * b4.z; c[6][3] += a1.z * b4.w;
            c[7][0] += a1.w * b4.x; c[7][1] += a1.w * b4.y; c[7][2] += a1.w * b4.z; c[7][3] += a1.w * b4.w;
        }
        __syncthreads();
    }

    #pragma unroll
    for (int i = 0; i < 8; ++i) {
        #pragma unroll
        for (int j = 0; j < 4; ++j) {
            int m = m0 + ty * 8 + i;
            int n = n0 + tx * 4 + j;
            float v = c[i][j] + bias[n];
            if (act == 1) v = (v > 20.0f) ? v : log1pf(expf(v));   // softplus
            C[(size_t)m * N + n] = v;
        }
    }
}

// ---------------- persistent recurrent kernel: SM-resident weights ----------------
// grid = NB (= #SMs), 512 threads, 1 CTA/SM (204.8 KB dynamic SMEM forces it).
// GRU weights in SMEM (fp16, per-warp slot); fc1/fc2 rows in registers.
// Loop reads no weights from L2/DRAM; biases hoisted; GI prefetched per phase.
__global__ void __launch_bounds__(512, 1) recurrent_kernel(
    const float* __restrict__ Whh,  const float* __restrict__ bhh,
    const float* __restrict__ fc1w, const float* __restrict__ fc1b,
    const float* __restrict__ fc2w, const float* __restrict__ fc2b,
    int NB)
{
    extern __shared__ __align__(16) char dsm[];
    float*  smv = reinterpret_cast<float*>(dsm);                 // [2048] staged vector
    __half* wg  = reinterpret_cast<__half*>(dsm + SMV_BYTES);    // [WSLOTS][3][2048]

    const int tid  = threadIdx.x;
    const int bid  = blockIdx.x;
    const int wid  = tid >> 5;
    const int lane = tid & 31;
    const unsigned nb = (unsigned)NB;
    unsigned barit = 0;

    const int  row  = wid * NB + bid;      // this warp's output row in every phase
    const bool live = (row < H_DIM);
    const int  kb   = lane * 8;            // per-lane K base (8 elements / uint4)

    __half* wrow = wg + (size_t)wid * 3 * H_DIM;

    // ---------- one-time: weights -> SMEM (GRU) and registers (fc1, fc2) ----------
    uint4 rf1[8], rf2[8];
    float b_r = 0.f, b_z = 0.f, b_n = 0.f, b_f1 = 0.f, b_f2 = 0.f;   // hoisted biases
    if (live) {
        #pragma unroll
        for (int g = 0; g < 3; ++g) {
            const float* src = Whh + (size_t)(row + g * H_DIM) * H_DIM;
            #pragma unroll
            for (int it = 0; it < 8; ++it) {
                const int k = kb + it * 256;
                float4 a = *reinterpret_cast<const float4*>(src + k);
                float4 b = *reinterpret_cast<const float4*>(src + k + 4);
                *reinterpret_cast<uint4*>(wrow + g * H_DIM + k) = pack8h(a, b);
            }
        }
        const float* s1p = fc1w + (size_t)row * H_DIM;
        const float* s2p = fc2w + (size_t)row * H_DIM;
        #pragma unroll
        for (int it = 0; it < 8; ++it) {
            const int k = kb + it * 256;
            float4 a1 = *reinterpret_cast<const float4*>(s1p + k);
            float4 b1 = *reinterpret_cast<const float4*>(s1p + k + 4);
            float4 a2 = *reinterpret_cast<const float4*>(s2p + k);
            float4 b2 = *reinterpret_cast<const float4*>(s2p + k + 4);
            rf1[it] = pack8h(a1, b1);
            rf2[it] = pack8h(a2, b2);
        }
        b_r  = bhh[row];
        b_z  = bhh[row + H_DIM];
        b_n  = bhh[row + 2 * H_DIM];
        b_f1 = fc1b[row];
        b_f2 = fc2b[row];
    } else {
        #pragma unroll
        for (int it = 0; it < 8; ++it) { rf1[it] = make_uint4(0,0,0,0); rf2[it] = make_uint4(0,0,0,0); }
    }
    // (each warp reads only its own SMEM slot; no block sync needed for weights)

    for (int t = 0; t < T_STEPS; ++t) {
        // ---------- stage h into smem ----------
        {
            float4 v = __ldcg(reinterpret_cast<const float4*>(g_h + tid * 4));
            *reinterpret_cast<float4*>(smv + tid * 4) = v;
        }
        __syncthreads();

        // ---------- P1: GRU cell (weights from SMEM) ----------
        if (live) {
            // prefetch GI[t] early so L2 latency overlaps the dot product
            float ir = 0.f, iz = 0.f, in_ = 0.f;
            if (lane == 0) {
                const float* gi = g_GI + (size_t)t * G3;
                ir  = __ldcg(gi + row);
                iz  = __ldcg(gi + row + H_DIM);
                in_ = __ldcg(gi + row + 2 * H_DIM);
            }
            float a0 = 0.f, a1 = 0.f, a2 = 0.f;
            #pragma unroll 2
            for (int it = 0; it < 8; ++it) {
                const int k = kb + it * 256;
                float4 s0 = *reinterpret_cast<const float4*>(smv + k);
                float4 s1 = *reinterpret_cast<const float4*>(smv + k + 4);
                uint4 u0 = *reinterpret_cast<const uint4*>(wrow + k);
                uint4 u1 = *reinterpret_cast<const uint4*>(wrow + H_DIM + k);
                uint4 u2 = *reinterpret_cast<const uint4*>(wrow + 2 * H_DIM + k);
                a0 += dot8(u0, s0, s1);
                a1 += dot8(u1, s0, s1);
                a2 += dot8(u2, s0, s1);
            }
            #pragma unroll
            for (int o = 16; o > 0; o >>= 1) {
                a0 += __shfl_xor_sync(0xffffffffu, a0, o);
                a1 += __shfl_xor_sync(0xffffffffu, a1, o);
                a2 += __shfl_xor_sync(0xffffffffu, a2, o);
            }
            if (lane == 0) {
                float r  = sigmoidf_(ir + a0 + b_r);
                float z  = sigmoidf_(iz + a1 + b_z);
                float n  = tanhf(in_ + r * (a2 + b_n));
                float hp = smv[row];
                float hnew = (1.0f - z) * n + z * hp;
                __stcg(&g_s0[row], eluf_(hnew));
            }
        }
        grid_bar(nb, barit);

        // ---------- stage s0 ----------
        {
            float4 v = __ldcg(reinterpret_cast<const float4*>(g_s0 + tid * 4));
            *reinterpret_cast<float4*>(smv + tid * 4) = v;
        }
        __syncthreads();

        // ---------- P2: fc1 (weights from registers) ----------
        if (live) {
            float a = 0.f;
            #pragma unroll
            for (int it = 0; it < 8; ++it) {
                const int k = kb + it * 256;
                float4 s0 = *reinterpret_cast<const float4*>(smv + k);
                float4 s1 = *reinterpret_cast<const float4*>(smv + k + 4);
                a += dot8(rf1[it], s0, s1);
            }
            #pragma unroll
            for (int o = 16; o > 0; o >>= 1) a += __shfl_xor_sync(0xffffffffu, a, o);
            if (lane == 0) __stcg(&g_s1[row], eluf_(a + b_f1));
        }
        grid_bar(nb, barit);

        // ---------- stage s1 ----------
        {
            float4 v = __ldcg(reinterpret_cast<const float4*>(g_s1 + tid * 4));
            *reinterpret_cast<float4*>(smv + tid * 4) = v;
        }
        __syncthreads();

        // ---------- P3: fc2 (weights from registers; result is next h and S[t]) ----------
        if (live) {
            float a = 0.f;
            #pragma unroll
            for (int it = 0; it < 8; ++it) {
                const int k = kb + it * 256;
                float4 s0 = *reinterpret_cast<const float4*>(smv + k);
                float4 s1 = *reinterpret_cast<const float4*>(smv + k + 4);
                a += dot8(rf2[it], s0, s1);
            }
            #pragma unroll
            for (int o = 16; o > 0; o >>= 1) a += __shfl_xor_sync(0xffffffffu, a, o);
            if (lane == 0) {
                float s2 = eluf_(a + b_f2);
                __stcg(&g_h[row], s2);
                g_S[(size_t)t * H_DIM + row] = s2;
            }
        }
        grid_bar(nb, barit);
    }
}

// ---------------- launch ----------------
extern "C" void kernel_launch(void* const* d_in, const int* in_sizes, int n_in,
                              void* d_out, int out_size)
{
    (void)n_in; (void)out_size;

    const float *actions, *state, *Wih, *Whh, *bih, *bhh;
    const float *fc1w, *fc1b, *fc2w, *fc2b, *meanw, *meanb, *stdw, *stdb;

    if (in_sizes[0] == T_STEPS * A_DIM) {
        // declaration order
        actions = (const float*)d_in[0];  state = (const float*)d_in[1];
        Wih     = (const float*)d_in[2];  Whh   = (const float*)d_in[3];
        bih     = (const float*)d_in[4];  bhh   = (const float*)d_in[5];
        fc1w    = (const float*)d_in[6];  fc1b  = (const float*)d_in[7];
        fc2w    = (const float*)d_in[8];  fc2b  = (const float*)d_in[9];
        meanw   = (const float*)d_in[10]; meanb = (const float*)d_in[11];
        stdw    = (const float*)d_in[12]; stdb  = (const float*)d_in[13];
    } else {
        // alphabetical: W_hh, W_ih, actions, b_hh, b_ih, fc1_b, fc1_w, fc2_b,
        //               fc2_w, mean_b, mean_w, state, std_b, std_w
        Whh     = (const float*)d_in[0];  Wih   = (const float*)d_in[1];
        actions = (const float*)d_in[2];  bhh   = (const float*)d_in[3];
        bih     = (const float*)d_in[4];  fc1b  = (const float*)d_in[5];
        fc1w    = (const float*)d_in[6];  fc2b  = (const float*)d_in[7];
        fc2w    = (const float*)d_in[8];  meanb = (const float*)d_in[9];
        meanw   = (const float*)d_in[10]; state = (const float*)d_in[11];
        stdb    = (const float*)d_in[12]; stdw  = (const float*)d_in[13];
    }
    float* out = (float*)d_out;

    int dev = 0;
    cudaGetDevice(&dev);
    int nsm = 148;
    cudaDeviceGetAttribute(&nsm, cudaDevAttrMultiProcessorCount, dev);
    if (nsm < 128) nsm = 128;         // mapping needs 16*NB >= 2048

    float* gi = nullptr;  cudaGetSymbolAddress((void**)&gi, g_GI);
    float* S  = nullptr;  cudaGetSymbolAddress((void**)&S,  g_S);

    // allow 204.8 KB dynamic SMEM (idempotent; host-side attribute, not a stream op)
    static bool attr_done = false;
    if (!attr_done) {
        cudaFuncSetAttribute(recurrent_kernel,
                             cudaFuncAttributeMaxDynamicSharedMemorySize, DSM_BYTES);
        attr_done = true;
    }

    // 1) reset barrier + initial state (every replay)
    reset_kernel<<<2, 1024>>>(state);

    // 2) precompute input gates: GI[t][g] = actions[t] . W_ih[g] + b_ih[g]
    {
        dim3 grid(G3 / 64, T_STEPS / 128);
        gemm_bias_act<<<grid, 256>>>(actions, Wih, bih, gi, T_STEPS, G3, A_DIM, 0);
    }

    // 3) sequential recurrence (persistent, SM-resident weights)
    recurrent_kernel<<<nsm, 512, DSM_BYTES>>>(Whh, bhh, fc1w, fc1b, fc2w, fc2b, nsm);

    // 4) deferred heads: means (identity) and stds (softplus)
    {
        dim3 grid(H_DIM / 64, T_STEPS / 128);
        gemm_bias_act<<<grid, 256>>>(S, meanw, meanb, out, T_STEPS, H_DIM, H_DIM, 0);
        gemm_bias_act<<<grid, 256>>>(S, stdw,  stdb,  out + (size_t)T_STEPS * H_DIM,
                                     T_STEPS, H_DIM, H_DIM, 1);
    }
}

// round 14
// speedup vs baseline: 1.9776x; 1.1962x over previous
#include <cuda_runtime.h>
#include <cuda_fp16.h>
#include <cstdint>
#include <math.h>

#define T_STEPS 1024
#define A_DIM   64
#define H_DIM   2048
#define G3      (3 * H_DIM)
#define WSLOTS  16                         // per-CTA warp slots for GRU weights in SMEM
#define SMV_BYTES (H_DIM * 2)              // staged fp16 vector (half)
#define DSM_BYTES (SMV_BYTES + WSLOTS * 3 * H_DIM * 2)   // 4096 + 196608 = 200704

// ---------------- persistent device scratch (no allocations allowed) ----------------
__device__ float    g_GI[T_STEPS * G3];       // precomputed input gates (incl. b_ih)
__device__ float    g_S [T_STEPS * H_DIM];    // s2 per step for deferred mean/std GEMMs
__device__ float    g_h [H_DIM];              // carried state (= previous s2)
__device__ float    g_s0[H_DIM];
__device__ float    g_s1[H_DIM];
__device__ unsigned g_barcnt;                 // monotonic grid barrier counter

// ---------------- helpers ----------------
__device__ __forceinline__ float sigmoidf_(float x) { return 1.0f / (1.0f + expf(-x)); }
__device__ __forceinline__ float eluf_(float x)     { return x > 0.0f ? x : expm1f(x); }

__device__ __forceinline__ uint4 pack8h(float4 a, float4 b)
{
    __half2 h0 = __floats2half2_rn(a.x, a.y);
    __half2 h1 = __floats2half2_rn(a.z, a.w);
    __half2 h2 = __floats2half2_rn(b.x, b.y);
    __half2 h3 = __floats2half2_rn(b.z, b.w);
    uint4 u;
    u.x = *reinterpret_cast<uint32_t*>(&h0);
    u.y = *reinterpret_cast<uint32_t*>(&h1);
    u.z = *reinterpret_cast<uint32_t*>(&h2);
    u.w = *reinterpret_cast<uint32_t*>(&h3);
    return u;
}

// half2 FMA of 8 packed fp16 weights with 8 packed fp16 vector values
__device__ __forceinline__ __half2 hfma8(uint4 w, uint4 s, __half2 acc)
{
    const __half2* wh = reinterpret_cast<const __half2*>(&w);
    const __half2* sh = reinterpret_cast<const __half2*>(&s);
    acc = __hfma2(wh[0], sh[0], acc);
    acc = __hfma2(wh[1], sh[1], acc);
    acc = __hfma2(wh[2], sh[2], acc);
    acc = __hfma2(wh[3], sh[3], acc);
    return acc;
}

// Grid-wide barrier: release-RED arrival; relaxed poll with nanosleep backoff;
// one acquire load on exit. No gpu-scope fence => no CCTL.IVALL L1 flush.
__device__ __forceinline__ void grid_bar(unsigned nb, unsigned& it)
{
    __syncthreads();
    it += 1;
    if (threadIdx.x == 0) {
        asm volatile("red.release.gpu.global.add.u32 [%0], 1;"
                     :: "l"(&g_barcnt) : "memory");
        const unsigned tgt = it * nb;
        unsigned v;
        asm volatile("ld.relaxed.gpu.global.u32 %0, [%1];"
                     : "=r"(v) : "l"(&g_barcnt) : "memory");
        while (v < tgt) {
            __nanosleep(64);
            asm volatile("ld.relaxed.gpu.global.u32 %0, [%1];"
                         : "=r"(v) : "l"(&g_barcnt) : "memory");
        }
        asm volatile("ld.acquire.gpu.global.u32 %0, [%1];"
                     : "=r"(v) : "l"(&g_barcnt) : "memory");
    }
    __syncthreads();
}

// ---------------- init kernel (each replay: resets barrier + state) ------
__global__ void reset_kernel(const float* __restrict__ state)
{
    int i = blockIdx.x * blockDim.x + threadIdx.x;
    if (i < H_DIM) g_h[i] = state[i];
    if (i == 0)    g_barcnt = 0u;
}

// ---------------- C[m][n] = act( sum_k A[m][k]*B[n][k] + bias[n] ) ----------
// BM=128, BN=64, BK=16, 256 threads, 8x4 micro-tile. All dims divide evenly.
__global__ void __launch_bounds__(256) gemm_bias_act(
    const float* __restrict__ A, const float* __restrict__ B,
    const float* __restrict__ bias, float* __restrict__ C,
    int M, int N, int K, int act)
{
    __shared__ __align__(16) float As[16][132];
    __shared__ __align__(16) float Bs[16][68];

    const int tid = threadIdx.x;
    const int tx  = tid & 15;
    const int ty  = tid >> 4;
    const int n0  = blockIdx.x * 64;
    const int m0  = blockIdx.y * 128;

    float c[8][4] = {};

    for (int k0 = 0; k0 < K; k0 += 16) {
        #pragma unroll
        for (int idx = tid; idx < 128 * 16; idx += 256) {
            int m  = idx >> 4;
            int kk = idx & 15;
            As[kk][m] = A[(size_t)(m0 + m) * K + k0 + kk];
        }
        #pragma unroll
        for (int idx = tid; idx < 64 * 16; idx += 256) {
            int m  = idx >> 4;
            int kk = idx & 15;
            Bs[kk][m] = B[(size_t)(n0 + m) * K + k0 + kk];
        }
        __syncthreads();

        #pragma unroll
        for (int kk = 0; kk < 16; ++kk) {
            float4 b4 = *reinterpret_cast<const float4*>(&Bs[kk][tx * 4]);
            float4 a0 = *reinterpret_cast<const float4*>(&As[kk][ty * 8]);
            float4 a1 = *reinterpret_cast<const float4*>(&As[kk][ty * 8 + 4]);
            c[0][0] += a0.x * b4.x; c[0][1] += a0.x * b4.y; c[0][2] += a0.x * b4.z; c[0][3] += a0.x * b4.w;
            c[1][0] += a0.y * b4.x; c[1][1] += a0.y * b4.y; c[1][2] += a0.y * b4.z; c[1][3] += a0.y * b4.w;
            c[2][0] += a0.z * b4.x; c[2][1] += a0.z * b4.y; c[2][2] += a0.z * b4.z; c[2][3] += a0.z * b4.w;
            c[3][0] += a0.w * b4.x; c[3][1] += a0.w * b4.y; c[3][2] += a0.w * b4.z; c[3][3] += a0.w * b4.w;
            c[4][0] += a1.x * b4.x; c[4][1] += a1.x * b4.y; c[4][2] += a1.x * b4.z; c[4][3] += a1.x * b4.w;
            c[5][0] += a1.y * b4.x; c[5][1] += a1.y * b4.y; c[5][2] += a1.y * b4.z; c[5][3] += a1.y * b4.w;
            c[6][0] += a1.z * b4.x; c[6][1] += a1.z * b4.y; c[6][2] += a1.z * b4.z; c[6][3] += a1.z * b4.w;
            c[7][0] += a1.w * b4.x; c[7][1] += a1.w * b4.y; c[7][2] += a1.w * b4.z; c[7][3] += a1.w * b4.w;
        }
        __syncthreads();
    }

    #pragma unroll
    for (int i = 0; i < 8; ++i) {
        #pragma unroll
        for (int j = 0; j < 4; ++j) {
            int m = m0 + ty * 8 + i;
            int n = n0 + tx * 4 + j;
            float v = c[i][j] + bias[n];
            if (act == 1) v = (v > 20.0f) ? v : log1pf(expf(v));   // softplus
            C[(size_t)m * N + n] = v;
        }
    }
}

// ---------------- persistent recurrent kernel: SM-resident weights, half2 math ------
// grid = NB (= #SMs), 512 threads, 1 CTA/SM (200.7 KB dynamic SMEM forces it).
// GRU weights in SMEM (fp16, per-warp slot); fc1/fc2 rows in registers (fp16).
// Vector staged in SMEM as fp16. Inner products via HFMA2 with short (8-product)
// fp16 chains flushed into fp32 accumulators every 2 iterations.
__global__ void __launch_bounds__(512, 1) recurrent_kernel(
    const float* __restrict__ Whh,  const float* __restrict__ bhh,
    const float* __restrict__ fc1w, const float* __restrict__ fc1b,
    const float* __restrict__ fc2w, const float* __restrict__ fc2b,
    int NB)
{
    extern __shared__ __align__(16) char dsm[];
    __half* smh  = reinterpret_cast<__half*>(dsm);               // [2048] staged fp16 vector
    __half* wg   = reinterpret_cast<__half*>(dsm + SMV_BYTES);   // [WSLOTS][3][2048]

    const int tid  = threadIdx.x;
    const int bid  = blockIdx.x;
    const int wid  = tid >> 5;
    const int lane = tid & 31;
    const unsigned nb = (unsigned)NB;
    unsigned barit = 0;

    const int  row  = wid * NB + bid;      // this warp's output row in every phase
    const bool live = (row < H_DIM);
    const int  kb   = lane * 8;            // per-lane K base (8 halfs per uint4)

    __half* wrow = wg + (size_t)wid * 3 * H_DIM;

    // ---------- one-time: weights -> SMEM (GRU) and registers (fc1, fc2) ----------
    uint4 rf1[8], rf2[8];
    float b_r = 0.f, b_z = 0.f, b_n = 0.f, b_f1 = 0.f, b_f2 = 0.f;
    if (live) {
        #pragma unroll
        for (int g = 0; g < 3; ++g) {
            const float* src = Whh + (size_t)(row + g * H_DIM) * H_DIM;
            #pragma unroll
            for (int it = 0; it < 8; ++it) {
                const int k = kb + it * 256;
                float4 a = *reinterpret_cast<const float4*>(src + k);
                float4 b = *reinterpret_cast<const float4*>(src + k + 4);
                *reinterpret_cast<uint4*>(wrow + g * H_DIM + k) = pack8h(a, b);
            }
        }
        const float* s1p = fc1w + (size_t)row * H_DIM;
        const float* s2p = fc2w + (size_t)row * H_DIM;
        #pragma unroll
        for (int it = 0; it < 8; ++it) {
            const int k = kb + it * 256;
            float4 a1 = *reinterpret_cast<const float4*>(s1p + k);
            float4 b1 = *reinterpret_cast<const float4*>(s1p + k + 4);
            float4 a2 = *reinterpret_cast<const float4*>(s2p + k);
            float4 b2 = *reinterpret_cast<const float4*>(s2p + k + 4);
            rf1[it] = pack8h(a1, b1);
            rf2[it] = pack8h(a2, b2);
        }
        b_r  = bhh[row];
        b_z  = bhh[row + H_DIM];
        b_n  = bhh[row + 2 * H_DIM];
        b_f1 = fc1b[row];
        b_f2 = fc2b[row];
    } else {
        #pragma unroll
        for (int it = 0; it < 8; ++it) { rf1[it] = make_uint4(0,0,0,0); rf2[it] = make_uint4(0,0,0,0); }
    }

    for (int t = 0; t < T_STEPS; ++t) {
        // ---------- stage h into smem as fp16 (512 threads x 4 floats) ----------
        {
            float4 v = __ldcg(reinterpret_cast<const float4*>(g_h + tid * 4));
            __half2 p0 = __floats2half2_rn(v.x, v.y);
            __half2 p1 = __floats2half2_rn(v.z, v.w);
            uint2 st;
            st.x = *reinterpret_cast<uint32_t*>(&p0);
            st.y = *reinterpret_cast<uint32_t*>(&p1);
            *reinterpret_cast<uint2*>(smh + tid * 4) = st;
        }
        __syncthreads();

        // ---------- P1: GRU cell (fp16 weights from SMEM, half2 math) ----------
        if (live) {
            // prefetch GI[t] and exact fp32 carry element early (L2 latency overlap)
            float ir = 0.f, iz = 0.f, in_ = 0.f, hp = 0.f;
            if (lane == 0) {
                const float* gi = g_GI + (size_t)t * G3;
                ir  = __ldcg(gi + row);
                iz  = __ldcg(gi + row + H_DIM);
                in_ = __ldcg(gi + row + 2 * H_DIM);
                hp  = __ldcg(g_h + row);
            }
            float a0 = 0.f, a1 = 0.f, a2 = 0.f;
            #pragma unroll
            for (int hf = 0; hf < 4; ++hf) {
                __half2 c0 = __float2half2_rn(0.f);
                __half2 c1 = __float2half2_rn(0.f);
                __half2 c2 = __float2half2_rn(0.f);
                #pragma unroll
                for (int j = 0; j < 2; ++j) {
                    const int k = kb + (hf * 2 + j) * 256;
                    uint4 sv = *reinterpret_cast<const uint4*>(smh + k);
                    uint4 u0 = *reinterpret_cast<const uint4*>(wrow + k);
                    uint4 u1 = *reinterpret_cast<const uint4*>(wrow + H_DIM + k);
                    uint4 u2 = *reinterpret_cast<const uint4*>(wrow + 2 * H_DIM + k);
                    c0 = hfma8(u0, sv, c0);
                    c1 = hfma8(u1, sv, c1);
                    c2 = hfma8(u2, sv, c2);
                }
                float2 f0 = __half22float2(c0); a0 += f0.x + f0.y;
                float2 f1 = __half22float2(c1); a1 += f1.x + f1.y;
                float2 f2 = __half22float2(c2); a2 += f2.x + f2.y;
            }
            #pragma unroll
            for (int o = 16; o > 0; o >>= 1) {
                a0 += __shfl_xor_sync(0xffffffffu, a0, o);
                a1 += __shfl_xor_sync(0xffffffffu, a1, o);
                a2 += __shfl_xor_sync(0xffffffffu, a2, o);
            }
            if (lane == 0) {
                float r  = sigmoidf_(ir + a0 + b_r);
                float z  = sigmoidf_(iz + a1 + b_z);
                float n  = tanhf(in_ + r * (a2 + b_n));
                float hnew = (1.0f - z) * n + z * hp;
                __stcg(&g_s0[row], eluf_(hnew));
            }
        }
        grid_bar(nb, barit);

        // ---------- stage s0 (fp16) ----------
        {
            float4 v = __ldcg(reinterpret_cast<const float4*>(g_s0 + tid * 4));
            __half2 p0 = __floats2half2_rn(v.x, v.y);
            __half2 p1 = __floats2half2_rn(v.z, v.w);
            uint2 st;
            st.x = *reinterpret_cast<uint32_t*>(&p0);
            st.y = *reinterpret_cast<uint32_t*>(&p1);
            *reinterpret_cast<uint2*>(smh + tid * 4) = st;
        }
        __syncthreads();

        // ---------- P2: fc1 (fp16 weights from registers) ----------
        if (live) {
            float a = 0.f;
            #pragma unroll
            for (int hf = 0; hf < 4; ++hf) {
                __half2 c = __float2half2_rn(0.f);
                #pragma unroll
                for (int j = 0; j < 2; ++j) {
                    const int it = hf * 2 + j;
                    const int k  = kb + it * 256;
                    uint4 sv = *reinterpret_cast<const uint4*>(smh + k);
                    c = hfma8(rf1[it], sv, c);
                }
                float2 f = __half22float2(c); a += f.x + f.y;
            }
            #pragma unroll
            for (int o = 16; o > 0; o >>= 1) a += __shfl_xor_sync(0xffffffffu, a, o);
            if (lane == 0) __stcg(&g_s1[row], eluf_(a + b_f1));
        }
        grid_bar(nb, barit);

        // ---------- stage s1 (fp16) ----------
        {
            float4 v = __ldcg(reinterpret_cast<const float4*>(g_s1 + tid * 4));
            __half2 p0 = __floats2half2_rn(v.x, v.y);
            __half2 p1 = __floats2half2_rn(v.z, v.w);
            uint2 st;
            st.x = *reinterpret_cast<uint32_t*>(&p0);
            st.y = *reinterpret_cast<uint32_t*>(&p1);
            *reinterpret_cast<uint2*>(smh + tid * 4) = st;
        }
        __syncthreads();

        // ---------- P3: fc2 (result is next h and S[t]) ----------
        if (live) {
            float a = 0.f;
            #pragma unroll
            for (int hf = 0; hf < 4; ++hf) {
                __half2 c = __float2half2_rn(0.f);
                #pragma unroll
                for (int j = 0; j < 2; ++j) {
                    const int it = hf * 2 + j;
                    const int k  = kb + it * 256;
                    uint4 sv = *reinterpret_cast<const uint4*>(smh + k);
                    c = hfma8(rf2[it], sv, c);
                }
                float2 f = __half22float2(c); a += f.x + f.y;
            }
            #pragma unroll
            for (int o = 16; o > 0; o >>= 1) a += __shfl_xor_sync(0xffffffffu, a, o);
            if (lane == 0) {
                float s2 = eluf_(a + b_f2);
                __stcg(&g_h[row], s2);
                g_S[(size_t)t * H_DIM + row] = s2;
            }
        }
        grid_bar(nb, barit);
    }
}

// ---------------- launch ----------------
extern "C" void kernel_launch(void* const* d_in, const int* in_sizes, int n_in,
                              void* d_out, int out_size)
{
    (void)n_in; (void)out_size;

    const float *actions, *state, *Wih, *Whh, *bih, *bhh;
    const float *fc1w, *fc1b, *fc2w, *fc2b, *meanw, *meanb, *stdw, *stdb;

    if (in_sizes[0] == T_STEPS * A_DIM) {
        // declaration order
        actions = (const float*)d_in[0];  state = (const float*)d_in[1];
        Wih     = (const float*)d_in[2];  Whh   = (const float*)d_in[3];
        bih     = (const float*)d_in[4];  bhh   = (const float*)d_in[5];
        fc1w    = (const float*)d_in[6];  fc1b  = (const float*)d_in[7];
        fc2w    = (const float*)d_in[8];  fc2b  = (const float*)d_in[9];
        meanw   = (const float*)d_in[10]; meanb = (const float*)d_in[11];
        stdw    = (const float*)d_in[12]; stdb  = (const float*)d_in[13];
    } else {
        // alphabetical: W_hh, W_ih, actions, b_hh, b_ih, fc1_b, fc1_w, fc2_b,
        //               fc2_w, mean_b, mean_w, state, std_b, std_w
        Whh     = (const float*)d_in[0];  Wih   = (const float*)d_in[1];
        actions = (const float*)d_in[2];  bhh   = (const float*)d_in[3];
        bih     = (const float*)d_in[4];  fc1b  = (const float*)d_in[5];
        fc1w    = (const float*)d_in[6];  fc2b  = (const float*)d_in[7];
        fc2w    = (const float*)d_in[8];  meanb = (const float*)d_in[9];
        meanw   = (const float*)d_in[10]; state = (const float*)d_in[11];
        stdb    = (const float*)d_in[12]; stdw  = (const float*)d_in[13];
    }
    float* out = (float*)d_out;

    int dev = 0;
    cudaGetDevice(&dev);
    int nsm = 148;
    cudaDeviceGetAttribute(&nsm, cudaDevAttrMultiProcessorCount, dev);
    if (nsm < 128) nsm = 128;         // mapping needs 16*NB >= 2048

    float* gi = nullptr;  cudaGetSymbolAddress((void**)&gi, g_GI);
    float* S  = nullptr;  cudaGetSymbolAddress((void**)&S,  g_S);

    static bool attr_done = false;
    if (!attr_done) {
        cudaFuncSetAttribute(recurrent_kernel,
                             cudaFuncAttributeMaxDynamicSharedMemorySize, DSM_BYTES);
        attr_done = true;
    }

    // 1) reset barrier + initial state (every replay)
    reset_kernel<<<2, 1024>>>(state);

    // 2) precompute input gates: GI[t][g] = actions[t] . W_ih[g] + b_ih[g]
    {
        dim3 grid(G3 / 64, T_STEPS / 128);
        gemm_bias_act<<<grid, 256>>>(actions, Wih, bih, gi, T_STEPS, G3, A_DIM, 0);
    }

    // 3) sequential recurrence (persistent, SM-resident weights, half2 math)
    recurrent_kernel<<<nsm, 512, DSM_BYTES>>>(Whh, bhh, fc1w, fc1b, fc2w, fc2b, nsm);

    // 4) deferred heads: means (identity) and stds (softplus)
    {
        dim3 grid(H_DIM / 64, T_STEPS / 128);
        gemm_bias_act<<<grid, 256>>>(S, meanw, meanb, out, T_STEPS, H_DIM, H_DIM, 0);
        gemm_bias_act<<<grid, 256>>>(S, stdw,  stdb,  out + (size_t)T_STEPS * H_DIM,
                                     T_STEPS, H_DIM, H_DIM, 1);
    }
}